// round 1
// baseline (speedup 1.0000x reference)
#include <cuda_runtime.h>

#define S_LEN 2048
#define BATCH 4
#define EMB   1024
#define NH    16
#define DK    64
#define MTOT  (BATCH * S_LEN)   // 8192

// Scratch (no allocations allowed): q, k, v projections + attention context.
__device__ float g_q[MTOT * EMB];
__device__ float g_k[MTOT * EMB];
__device__ float g_v[MTOT * EMB];
__device__ float g_ctx[MTOT * EMB];

// ---------------------------------------------------------------------------
// C[M,N] = A[M,K] * B[N,K]^T   (M=MTOT, N=K=EMB fixed)
// 128x128 tile, BK=16, 256 threads, 8x8 per thread (2x2 quads of 4x4).
// ---------------------------------------------------------------------------
__global__ __launch_bounds__(256) void gemm_nt(const float* __restrict__ A,
                                               const float* __restrict__ B,
                                               float* __restrict__ C)
{
    const int K = EMB, N = EMB;
    __shared__ float sA[16][132];
    __shared__ float sB[16][132];

    const int tid = threadIdx.x;
    const int bm = blockIdx.y * 128;
    const int bn = blockIdx.x * 128;
    const int tr0 = (tid >> 4) << 2;   // 0..60 step 4
    const int tc0 = (tid & 15) << 2;   // 0..60 step 4

    float acc[8][8];
#pragma unroll
    for (int i = 0; i < 8; i++)
#pragma unroll
        for (int j = 0; j < 8; j++) acc[i][j] = 0.f;

    const float* Aptr = A + (size_t)bm * K;
    const float* Bptr = B + (size_t)bn * K;

    for (int k0 = 0; k0 < K; k0 += 16) {
#pragma unroll
        for (int i = 0; i < 2; i++) {
            int v = tid + (i << 8);           // 0..511
            int r  = v >> 2;                  // 0..127
            int kc = (v & 3) << 2;            // 0,4,8,12
            float4 a4 = *(const float4*)(Aptr + (size_t)r * K + k0 + kc);
            sA[kc + 0][r] = a4.x; sA[kc + 1][r] = a4.y;
            sA[kc + 2][r] = a4.z; sA[kc + 3][r] = a4.w;
            float4 b4 = *(const float4*)(Bptr + (size_t)r * K + k0 + kc);
            sB[kc + 0][r] = b4.x; sB[kc + 1][r] = b4.y;
            sB[kc + 2][r] = b4.z; sB[kc + 3][r] = b4.w;
        }
        __syncthreads();

#pragma unroll
        for (int kk = 0; kk < 16; kk++) {
            float ra[8], rb[8];
            *(float4*)&ra[0] = *(const float4*)&sA[kk][tr0];
            *(float4*)&ra[4] = *(const float4*)&sA[kk][tr0 + 64];
            *(float4*)&rb[0] = *(const float4*)&sB[kk][tc0];
            *(float4*)&rb[4] = *(const float4*)&sB[kk][tc0 + 64];
#pragma unroll
            for (int i = 0; i < 8; i++)
#pragma unroll
                for (int j = 0; j < 8; j++)
                    acc[i][j] += ra[i] * rb[j];
        }
        __syncthreads();
    }

#pragma unroll
    for (int i = 0; i < 8; i++) {
        int r = bm + ((i < 4) ? (tr0 + i) : (64 + tr0 + i - 4));
        float* cp = C + (size_t)r * N + bn;
        *(float4*)(cp + tc0)      = make_float4(acc[i][0], acc[i][1], acc[i][2], acc[i][3]);
        *(float4*)(cp + tc0 + 64) = make_float4(acc[i][4], acc[i][5], acc[i][6], acc[i][7]);
    }
}

// ---------------------------------------------------------------------------
// Flash attention: one thread per query row. grid = (S/128, B*H), block = 128.
// q row + O accumulator live in registers (all d-loops fully unrolled so the
// arrays stay register-resident). K/V tiles of 16 rows in smem; per-thread
// score stash in smem row of stride 17 (bank-conflict-free).
// ---------------------------------------------------------------------------
__global__ __launch_bounds__(128) void flash_attn(const float* __restrict__ Qp,
                                                  const float* __restrict__ Kp,
                                                  const float* __restrict__ Vp,
                                                  float* __restrict__ Op)
{
    const int bh = blockIdx.y;
    const int b = bh >> 4;
    const int h = bh & 15;
    const int tid = threadIdx.x;
    const int row = blockIdx.x * 128 + tid;

    const size_t baseQ = ((size_t)(b * S_LEN + row)) * EMB + h * DK;
    const size_t baseK = ((size_t)b * S_LEN) * EMB + h * DK;

    float q[DK];
#pragma unroll
    for (int d = 0; d < DK; d += 4) {
        float4 t = *(const float4*)(Qp + baseQ + d);
        q[d] = t.x; q[d + 1] = t.y; q[d + 2] = t.z; q[d + 3] = t.w;
    }

    float o[DK];
#pragma unroll
    for (int d = 0; d < DK; d++) o[d] = 0.f;
    float m = -1e30f, l = 0.f;

    __shared__ float ks[16][DK + 4];
    __shared__ float vs[16][DK + 4];
    __shared__ float ss[128][17];

    for (int t0 = 0; t0 < S_LEN; t0 += 16) {
        // Load K/V tiles: 16 rows x 16 float4 each; 128 threads -> 2 vec4 each.
#pragma unroll
        for (int i = 0; i < 2; i++) {
            int v  = tid + (i << 7);     // 0..255
            int j  = v >> 4;             // 0..15
            int d4 = (v & 15) << 2;      // 0..60
            float4 kk = *(const float4*)(Kp + baseK + (size_t)(t0 + j) * EMB + d4);
            ks[j][d4 + 0] = kk.x; ks[j][d4 + 1] = kk.y;
            ks[j][d4 + 2] = kk.z; ks[j][d4 + 3] = kk.w;
            float4 vv = *(const float4*)(Vp + baseK + (size_t)(t0 + j) * EMB + d4);
            vs[j][d4 + 0] = vv.x; vs[j][d4 + 1] = vv.y;
            vs[j][d4 + 2] = vv.z; vs[j][d4 + 3] = vv.w;
        }
        __syncthreads();

        // Scores for this 16-column tile.
        float smax = -1e30f;
        for (int j = 0; j < 16; j++) {
            float a0 = 0.f, a1 = 0.f, a2 = 0.f, a3 = 0.f;
#pragma unroll
            for (int d = 0; d < DK; d += 4) {
                a0 += q[d]     * ks[j][d];
                a1 += q[d + 1] * ks[j][d + 1];
                a2 += q[d + 2] * ks[j][d + 2];
                a3 += q[d + 3] * ks[j][d + 3];
            }
            float sj = ((a0 + a1) + (a2 + a3)) * 0.125f;  // / sqrt(64)
            ss[tid][j] = sj;
            smax = fmaxf(smax, sj);
        }

        float mnew = fmaxf(m, smax);
        float corr = __expf(m - mnew);
        l *= corr;
#pragma unroll
        for (int d = 0; d < DK; d++) o[d] *= corr;

        for (int j = 0; j < 16; j++) {
            float p = __expf(ss[tid][j] - mnew);
            l += p;
#pragma unroll
            for (int d = 0; d < DK; d++) o[d] += p * vs[j][d];
        }
        m = mnew;
        __syncthreads();
    }

    float inv = 1.0f / l;
    float* outp = Op + baseQ;
#pragma unroll
    for (int d = 0; d < DK; d += 4) {
        float4 t;
        t.x = o[d] * inv; t.y = o[d + 1] * inv;
        t.z = o[d + 2] * inv; t.w = o[d + 3] * inv;
        *(float4*)(outp + d) = t;
    }
}

// ---------------------------------------------------------------------------
extern "C" void kernel_launch(void* const* d_in, const int* in_sizes, int n_in,
                              void* d_out, int out_size)
{
    (void)in_sizes; (void)n_in; (void)out_size;
    const float* Q  = (const float*)d_in[0];
    const float* Kx = (const float*)d_in[1];
    const float* V  = (const float*)d_in[2];
    // d_in[3] = mask (unused)
    const float* Wq = (const float*)d_in[4];
    const float* Wk = (const float*)d_in[5];
    const float* Wv = (const float*)d_in[6];
    const float* Wo = (const float*)d_in[7];
    float* out = (float*)d_out;

    float *gq, *gk, *gv, *gctx;
    cudaGetSymbolAddress((void**)&gq,   g_q);
    cudaGetSymbolAddress((void**)&gk,   g_k);
    cudaGetSymbolAddress((void**)&gv,   g_v);
    cudaGetSymbolAddress((void**)&gctx, g_ctx);

    dim3 gg(EMB / 128, MTOT / 128);   // (8, 64)
    gemm_nt<<<gg, 256>>>(Q,  Wq, gq);
    gemm_nt<<<gg, 256>>>(Kx, Wk, gk);
    gemm_nt<<<gg, 256>>>(V,  Wv, gv);

    dim3 ga(S_LEN / 128, BATCH * NH); // (16, 64)
    flash_attn<<<ga, 128>>>(gq, gk, gv, gctx);

    gemm_nt<<<gg, 256>>>(gctx, Wo, out);
}

// round 2
// speedup vs baseline: 1.1865x; 1.1865x over previous
#include <cuda_runtime.h>
#include <cuda_bf16.h>
#include <cstdint>

#define S_LEN 2048
#define BATCH 4
#define EMB   1024
#define NH    16
#define DK    64
#define MTOT  (BATCH * S_LEN)   // 8192

// Scratch (no allocations allowed): q, k, v projections + attention context.
__device__ float g_q[MTOT * EMB];
__device__ float g_k[MTOT * EMB];
__device__ float g_v[MTOT * EMB];
__device__ float g_ctx[MTOT * EMB];

// ---------------------------------------------------------------------------
// Split-bf16 tensor-core GEMM:  C[M,N] = A[M,K] * B[N,K]^T  (fp32 in/out)
// A,B rounded to bf16 hi + bf16 lo;  C += Ahi*Bhi + Alo*Bhi + Ahi*Blo.
// CTA tile 128x128, BK=32, 256 threads (8 warps, 2x4 grid of 64x32 warp tiles).
// smem rows padded to 40 bf16 (80 B: 16B-aligned, ldmatrix conflict-free).
// ---------------------------------------------------------------------------
#define BM 128
#define BN 128
#define BK 32
#define SSTR 40   // padded bf16 row stride

__device__ __forceinline__ uint32_t pack2(float a, float b) {
    __nv_bfloat162 t = __floats2bfloat162_rn(a, b);
    return *reinterpret_cast<uint32_t*>(&t);
}

__device__ __forceinline__ void ldm_x4(uint32_t& r0, uint32_t& r1,
                                       uint32_t& r2, uint32_t& r3, uint32_t addr) {
    asm volatile("ldmatrix.sync.aligned.m8n8.x4.shared.b16 {%0,%1,%2,%3}, [%4];"
                 : "=r"(r0), "=r"(r1), "=r"(r2), "=r"(r3) : "r"(addr));
}

__device__ __forceinline__ void mma16816(float& c0, float& c1, float& c2, float& c3,
                                         uint32_t a0, uint32_t a1, uint32_t a2, uint32_t a3,
                                         uint32_t b0, uint32_t b1) {
    asm volatile("mma.sync.aligned.m16n8k16.row.col.f32.bf16.bf16.f32 "
                 "{%0,%1,%2,%3},{%4,%5,%6,%7},{%8,%9},{%0,%1,%2,%3};"
                 : "+f"(c0), "+f"(c1), "+f"(c2), "+f"(c3)
                 : "r"(a0), "r"(a1), "r"(a2), "r"(a3), "r"(b0), "r"(b1));
}

__global__ __launch_bounds__(256) void gemm_nt_tc(const float* __restrict__ A,
                                                  const float* __restrict__ B,
                                                  float* __restrict__ C)
{
    const int K = EMB, N = EMB;
    __shared__ __align__(16) __nv_bfloat16 sAh[BM][SSTR];
    __shared__ __align__(16) __nv_bfloat16 sAl[BM][SSTR];
    __shared__ __align__(16) __nv_bfloat16 sBh[BN][SSTR];
    __shared__ __align__(16) __nv_bfloat16 sBl[BN][SSTR];

    const int tid  = threadIdx.x;
    const int lane = tid & 31;
    const int wid  = tid >> 5;
    const int wm = (wid & 1) * 64;   // warp m offset in tile
    const int wn = (wid >> 1) * 32;  // warp n offset in tile

    const int bm = blockIdx.y * BM;
    const int bn = blockIdx.x * BN;

    const float* Aptr = A + (size_t)bm * K;
    const float* Bptr = B + (size_t)bn * K;

    // Each thread loads 4 float4 of A and 4 of B per BK=32 slab.
    // v = tid + 256*i : row = v>>3 (0..127), c4 = v&7 (8 float4 per 32-float row)
    float4 pa[4], pb[4];

    const int lrow = lane & 15;
    const int lcol = (lane >> 4) << 3;  // 0 or 8

    uint32_t base_Ah = (uint32_t)__cvta_generic_to_shared(&sAh[0][0]);
    uint32_t base_Al = (uint32_t)__cvta_generic_to_shared(&sAl[0][0]);
    uint32_t base_Bh = (uint32_t)__cvta_generic_to_shared(&sBh[0][0]);
    uint32_t base_Bl = (uint32_t)__cvta_generic_to_shared(&sBl[0][0]);

    float acc[4][4][4];
#pragma unroll
    for (int i = 0; i < 4; i++)
#pragma unroll
        for (int j = 0; j < 4; j++)
#pragma unroll
            for (int c = 0; c < 4; c++) acc[i][j][c] = 0.f;

#define LOAD_TILE(k0)                                                          \
    {                                                                          \
        _Pragma("unroll")                                                      \
        for (int i = 0; i < 4; i++) {                                          \
            int v = tid + (i << 8);                                            \
            int r = v >> 3, c4 = (v & 7) << 2;                                 \
            pa[i] = *(const float4*)(Aptr + (size_t)r * K + (k0) + c4);        \
            pb[i] = *(const float4*)(Bptr + (size_t)r * K + (k0) + c4);        \
        }                                                                      \
    }

#define STORE_TILE()                                                           \
    {                                                                          \
        _Pragma("unroll")                                                      \
        for (int i = 0; i < 4; i++) {                                          \
            int v = tid + (i << 8);                                            \
            int r = v >> 3, c4 = (v & 7) << 2;                                 \
            float4 f = pa[i];                                                  \
            float h0 = __bfloat162float(__float2bfloat16_rn(f.x));             \
            float h1 = __bfloat162float(__float2bfloat16_rn(f.y));             \
            float h2 = __bfloat162float(__float2bfloat16_rn(f.z));             \
            float h3 = __bfloat162float(__float2bfloat16_rn(f.w));             \
            *(uint2*)&sAh[r][c4] = make_uint2(pack2(f.x, f.y), pack2(f.z, f.w));\
            *(uint2*)&sAl[r][c4] = make_uint2(pack2(f.x - h0, f.y - h1),       \
                                              pack2(f.z - h2, f.w - h3));      \
            f = pb[i];                                                         \
            h0 = __bfloat162float(__float2bfloat16_rn(f.x));                   \
            h1 = __bfloat162float(__float2bfloat16_rn(f.y));                   \
            h2 = __bfloat162float(__float2bfloat16_rn(f.z));                   \
            h3 = __bfloat162float(__float2bfloat16_rn(f.w));                   \
            *(uint2*)&sBh[r][c4] = make_uint2(pack2(f.x, f.y), pack2(f.z, f.w));\
            *(uint2*)&sBl[r][c4] = make_uint2(pack2(f.x - h0, f.y - h1),       \
                                              pack2(f.z - h2, f.w - h3));      \
        }                                                                      \
    }

    LOAD_TILE(0);
    STORE_TILE();
    __syncthreads();

    const int NIT = K / BK;  // 32
    for (int it = 0; it < NIT; it++) {
        if (it + 1 < NIT) LOAD_TILE((it + 1) * BK);

#pragma unroll
        for (int ks = 0; ks < BK; ks += 16) {
            // B fragments: two ldmatrix.x4 per hi/lo, covering n = wn..wn+31
            uint32_t bh[2][4], bl[2][4];
#pragma unroll
            for (int p = 0; p < 2; p++) {
                uint32_t off = (uint32_t)((wn + p * 16 + lrow) * SSTR + ks + lcol) * 2;
                ldm_x4(bh[p][0], bh[p][1], bh[p][2], bh[p][3], base_Bh + off);
                ldm_x4(bl[p][0], bl[p][1], bl[p][2], bl[p][3], base_Bl + off);
            }
            // A fragments + MMAs per m16 tile
#pragma unroll
            for (int mt = 0; mt < 4; mt++) {
                uint32_t off = (uint32_t)((wm + mt * 16 + lrow) * SSTR + ks + lcol) * 2;
                uint32_t ah0, ah1, ah2, ah3, al0, al1, al2, al3;
                ldm_x4(ah0, ah1, ah2, ah3, base_Ah + off);
                ldm_x4(al0, al1, al2, al3, base_Al + off);
#pragma unroll
                for (int p = 0; p < 2; p++) {
                    // n8 tile 0 of pair: b regs {R0,R2}; tile 1: {R1,R3}
                    float* c0 = acc[mt][p * 2];
                    mma16816(c0[0], c0[1], c0[2], c0[3],
                             ah0, ah1, ah2, ah3, bh[p][0], bh[p][2]);
                    mma16816(c0[0], c0[1], c0[2], c0[3],
                             al0, al1, al2, al3, bh[p][0], bh[p][2]);
                    mma16816(c0[0], c0[1], c0[2], c0[3],
                             ah0, ah1, ah2, ah3, bl[p][0], bl[p][2]);
                    float* c1 = acc[mt][p * 2 + 1];
                    mma16816(c1[0], c1[1], c1[2], c1[3],
                             ah0, ah1, ah2, ah3, bh[p][1], bh[p][3]);
                    mma16816(c1[0], c1[1], c1[2], c1[3],
                             al0, al1, al2, al3, bh[p][1], bh[p][3]);
                    mma16816(c1[0], c1[1], c1[2], c1[3],
                             ah0, ah1, ah2, ah3, bl[p][1], bl[p][3]);
                }
            }
        }
        __syncthreads();
        if (it + 1 < NIT) {
            STORE_TILE();
            __syncthreads();
        }
    }

    // Epilogue: c fragment layout: c0,c1 at (row=lane>>2, col=(lane&3)*2 +0/1),
    // c2,c3 at row+8.
#pragma unroll
    for (int mt = 0; mt < 4; mt++) {
#pragma unroll
        for (int nt = 0; nt < 4; nt++) {
            int gr = bm + wm + mt * 16 + (lane >> 2);
            int gc = bn + wn + nt * 8 + (lane & 3) * 2;
            float* c = acc[mt][nt];
            *(float2*)(C + (size_t)gr * N + gc)       = make_float2(c[0], c[1]);
            *(float2*)(C + (size_t)(gr + 8) * N + gc) = make_float2(c[2], c[3]);
        }
    }
#undef LOAD_TILE
#undef STORE_TILE
}

// ---------------------------------------------------------------------------
// Flash attention: one thread per query row (unchanged from R1).
// ---------------------------------------------------------------------------
__global__ __launch_bounds__(128) void flash_attn(const float* __restrict__ Qp,
                                                  const float* __restrict__ Kp,
                                                  const float* __restrict__ Vp,
                                                  float* __restrict__ Op)
{
    const int bh = blockIdx.y;
    const int b = bh >> 4;
    const int h = bh & 15;
    const int tid = threadIdx.x;
    const int row = blockIdx.x * 128 + tid;

    const size_t baseQ = ((size_t)(b * S_LEN + row)) * EMB + h * DK;
    const size_t baseK = ((size_t)b * S_LEN) * EMB + h * DK;

    float q[DK];
#pragma unroll
    for (int d = 0; d < DK; d += 4) {
        float4 t = *(const float4*)(Qp + baseQ + d);
        q[d] = t.x; q[d + 1] = t.y; q[d + 2] = t.z; q[d + 3] = t.w;
    }

    float o[DK];
#pragma unroll
    for (int d = 0; d < DK; d++) o[d] = 0.f;
    float m = -1e30f, l = 0.f;

    __shared__ float ks[16][DK + 4];
    __shared__ float vs[16][DK + 4];
    __shared__ float ss[128][17];

    for (int t0 = 0; t0 < S_LEN; t0 += 16) {
#pragma unroll
        for (int i = 0; i < 2; i++) {
            int v  = tid + (i << 7);
            int j  = v >> 4;
            int d4 = (v & 15) << 2;
            float4 kk = *(const float4*)(Kp + baseK + (size_t)(t0 + j) * EMB + d4);
            ks[j][d4 + 0] = kk.x; ks[j][d4 + 1] = kk.y;
            ks[j][d4 + 2] = kk.z; ks[j][d4 + 3] = kk.w;
            float4 vv = *(const float4*)(Vp + baseK + (size_t)(t0 + j) * EMB + d4);
            vs[j][d4 + 0] = vv.x; vs[j][d4 + 1] = vv.y;
            vs[j][d4 + 2] = vv.z; vs[j][d4 + 3] = vv.w;
        }
        __syncthreads();

        float smax = -1e30f;
        for (int j = 0; j < 16; j++) {
            float a0 = 0.f, a1 = 0.f, a2 = 0.f, a3 = 0.f;
#pragma unroll
            for (int d = 0; d < DK; d += 4) {
                a0 += q[d]     * ks[j][d];
                a1 += q[d + 1] * ks[j][d + 1];
                a2 += q[d + 2] * ks[j][d + 2];
                a3 += q[d + 3] * ks[j][d + 3];
            }
            float sj = ((a0 + a1) + (a2 + a3)) * 0.125f;
            ss[tid][j] = sj;
            smax = fmaxf(smax, sj);
        }

        float mnew = fmaxf(m, smax);
        float corr = __expf(m - mnew);
        l *= corr;
#pragma unroll
        for (int d = 0; d < DK; d++) o[d] *= corr;

        for (int j = 0; j < 16; j++) {
            float p = __expf(ss[tid][j] - mnew);
            l += p;
#pragma unroll
            for (int d = 0; d < DK; d++) o[d] += p * vs[j][d];
        }
        m = mnew;
        __syncthreads();
    }

    float inv = 1.0f / l;
    float* outp = Op + baseQ;
#pragma unroll
    for (int d = 0; d < DK; d += 4) {
        float4 t;
        t.x = o[d] * inv; t.y = o[d + 1] * inv;
        t.z = o[d + 2] * inv; t.w = o[d + 3] * inv;
        *(float4*)(outp + d) = t;
    }
}

// ---------------------------------------------------------------------------
extern "C" void kernel_launch(void* const* d_in, const int* in_sizes, int n_in,
                              void* d_out, int out_size)
{
    (void)in_sizes; (void)n_in; (void)out_size;
    const float* Q  = (const float*)d_in[0];
    const float* Kx = (const float*)d_in[1];
    const float* V  = (const float*)d_in[2];
    // d_in[3] = mask (unused)
    const float* Wq = (const float*)d_in[4];
    const float* Wk = (const float*)d_in[5];
    const float* Wv = (const float*)d_in[6];
    const float* Wo = (const float*)d_in[7];
    float* out = (float*)d_out;

    float *gq, *gk, *gv, *gctx;
    cudaGetSymbolAddress((void**)&gq,   g_q);
    cudaGetSymbolAddress((void**)&gk,   g_k);
    cudaGetSymbolAddress((void**)&gv,   g_v);
    cudaGetSymbolAddress((void**)&gctx, g_ctx);

    dim3 gg(EMB / BN, MTOT / BM);     // (8, 64)
    gemm_nt_tc<<<gg, 256>>>(Q,  Wq, gq);
    gemm_nt_tc<<<gg, 256>>>(Kx, Wk, gk);
    gemm_nt_tc<<<gg, 256>>>(V,  Wv, gv);

    dim3 ga(S_LEN / 128, BATCH * NH); // (16, 64)
    flash_attn<<<ga, 128>>>(gq, gk, gv, gctx);

    gemm_nt_tc<<<gg, 256>>>(gctx, Wo, out);
}

// round 3
// speedup vs baseline: 2.7301x; 2.3010x over previous
#include <cuda_runtime.h>
#include <cuda_bf16.h>
#include <cstdint>

#define S_LEN 2048
#define BATCH 4
#define EMB   1024
#define NH    16
#define DK    64
#define MTOT  (BATCH * S_LEN)   // 8192

// Scratch (no allocations allowed): q, k, v projections + attention context.
__device__ float g_q[MTOT * EMB];
__device__ float g_k[MTOT * EMB];
__device__ float g_v[MTOT * EMB];
__device__ float g_ctx[MTOT * EMB];

__device__ __forceinline__ uint32_t pack2(float a, float b) {
    __nv_bfloat162 t = __floats2bfloat162_rn(a, b);
    return *reinterpret_cast<uint32_t*>(&t);
}

__device__ __forceinline__ void ldm_x4(uint32_t& r0, uint32_t& r1,
                                       uint32_t& r2, uint32_t& r3, uint32_t addr) {
    asm volatile("ldmatrix.sync.aligned.m8n8.x4.shared.b16 {%0,%1,%2,%3}, [%4];"
                 : "=r"(r0), "=r"(r1), "=r"(r2), "=r"(r3) : "r"(addr));
}

__device__ __forceinline__ void ldm_x4_t(uint32_t& r0, uint32_t& r1,
                                         uint32_t& r2, uint32_t& r3, uint32_t addr) {
    asm volatile("ldmatrix.sync.aligned.m8n8.x4.trans.shared.b16 {%0,%1,%2,%3}, [%4];"
                 : "=r"(r0), "=r"(r1), "=r"(r2), "=r"(r3) : "r"(addr));
}

__device__ __forceinline__ void mma16816(float& c0, float& c1, float& c2, float& c3,
                                         uint32_t a0, uint32_t a1, uint32_t a2, uint32_t a3,
                                         uint32_t b0, uint32_t b1) {
    asm volatile("mma.sync.aligned.m16n8k16.row.col.f32.bf16.bf16.f32 "
                 "{%0,%1,%2,%3},{%4,%5,%6,%7},{%8,%9},{%0,%1,%2,%3};"
                 : "+f"(c0), "+f"(c1), "+f"(c2), "+f"(c3)
                 : "r"(a0), "r"(a1), "r"(a2), "r"(a3), "r"(b0), "r"(b1));
}

// ---------------------------------------------------------------------------
// Split-bf16 tensor-core GEMM:  C[M,N] = A[M,K] * B[N,K]^T  (fp32 in/out)
// (unchanged from R2 — validated)
// ---------------------------------------------------------------------------
#define BM 128
#define BN 128
#define BK 32
#define SSTR 40

__global__ __launch_bounds__(256) void gemm_nt_tc(const float* __restrict__ A,
                                                  const float* __restrict__ B,
                                                  float* __restrict__ C)
{
    const int K = EMB, N = EMB;
    __shared__ __align__(16) __nv_bfloat16 sAh[BM][SSTR];
    __shared__ __align__(16) __nv_bfloat16 sAl[BM][SSTR];
    __shared__ __align__(16) __nv_bfloat16 sBh[BN][SSTR];
    __shared__ __align__(16) __nv_bfloat16 sBl[BN][SSTR];

    const int tid  = threadIdx.x;
    const int lane = tid & 31;
    const int wid  = tid >> 5;
    const int wm = (wid & 1) * 64;
    const int wn = (wid >> 1) * 32;

    const int bm = blockIdx.y * BM;
    const int bn = blockIdx.x * BN;

    const float* Aptr = A + (size_t)bm * K;
    const float* Bptr = B + (size_t)bn * K;

    float4 pa[4], pb[4];

    const int lrow = lane & 15;
    const int lcol = (lane >> 4) << 3;

    uint32_t base_Ah = (uint32_t)__cvta_generic_to_shared(&sAh[0][0]);
    uint32_t base_Al = (uint32_t)__cvta_generic_to_shared(&sAl[0][0]);
    uint32_t base_Bh = (uint32_t)__cvta_generic_to_shared(&sBh[0][0]);
    uint32_t base_Bl = (uint32_t)__cvta_generic_to_shared(&sBl[0][0]);

    float acc[4][4][4];
#pragma unroll
    for (int i = 0; i < 4; i++)
#pragma unroll
        for (int j = 0; j < 4; j++)
#pragma unroll
            for (int c = 0; c < 4; c++) acc[i][j][c] = 0.f;

#define LOAD_TILE(k0)                                                          \
    {                                                                          \
        _Pragma("unroll")                                                      \
        for (int i = 0; i < 4; i++) {                                          \
            int v = tid + (i << 8);                                            \
            int r = v >> 3, c4 = (v & 7) << 2;                                 \
            pa[i] = *(const float4*)(Aptr + (size_t)r * K + (k0) + c4);        \
            pb[i] = *(const float4*)(Bptr + (size_t)r * K + (k0) + c4);        \
        }                                                                      \
    }

#define STORE_TILE()                                                           \
    {                                                                          \
        _Pragma("unroll")                                                      \
        for (int i = 0; i < 4; i++) {                                          \
            int v = tid + (i << 8);                                            \
            int r = v >> 3, c4 = (v & 7) << 2;                                 \
            float4 f = pa[i];                                                  \
            float h0 = __bfloat162float(__float2bfloat16_rn(f.x));             \
            float h1 = __bfloat162float(__float2bfloat16_rn(f.y));             \
            float h2 = __bfloat162float(__float2bfloat16_rn(f.z));             \
            float h3 = __bfloat162float(__float2bfloat16_rn(f.w));             \
            *(uint2*)&sAh[r][c4] = make_uint2(pack2(f.x, f.y), pack2(f.z, f.w));\
            *(uint2*)&sAl[r][c4] = make_uint2(pack2(f.x - h0, f.y - h1),       \
                                              pack2(f.z - h2, f.w - h3));      \
            f = pb[i];                                                         \
            h0 = __bfloat162float(__float2bfloat16_rn(f.x));                   \
            h1 = __bfloat162float(__float2bfloat16_rn(f.y));                   \
            h2 = __bfloat162float(__float2bfloat16_rn(f.z));                   \
            h3 = __bfloat162float(__float2bfloat16_rn(f.w));                   \
            *(uint2*)&sBh[r][c4] = make_uint2(pack2(f.x, f.y), pack2(f.z, f.w));\
            *(uint2*)&sBl[r][c4] = make_uint2(pack2(f.x - h0, f.y - h1),       \
                                              pack2(f.z - h2, f.w - h3));      \
        }                                                                      \
    }

    LOAD_TILE(0);
    STORE_TILE();
    __syncthreads();

    const int NIT = K / BK;
    for (int it = 0; it < NIT; it++) {
        if (it + 1 < NIT) LOAD_TILE((it + 1) * BK);

#pragma unroll
        for (int ks = 0; ks < BK; ks += 16) {
            uint32_t bh[2][4], bl[2][4];
#pragma unroll
            for (int p = 0; p < 2; p++) {
                uint32_t off = (uint32_t)((wn + p * 16 + lrow) * SSTR + ks + lcol) * 2;
                ldm_x4(bh[p][0], bh[p][1], bh[p][2], bh[p][3], base_Bh + off);
                ldm_x4(bl[p][0], bl[p][1], bl[p][2], bl[p][3], base_Bl + off);
            }
#pragma unroll
            for (int mt = 0; mt < 4; mt++) {
                uint32_t off = (uint32_t)((wm + mt * 16 + lrow) * SSTR + ks + lcol) * 2;
                uint32_t ah0, ah1, ah2, ah3, al0, al1, al2, al3;
                ldm_x4(ah0, ah1, ah2, ah3, base_Ah + off);
                ldm_x4(al0, al1, al2, al3, base_Al + off);
#pragma unroll
                for (int p = 0; p < 2; p++) {
                    float* c0 = acc[mt][p * 2];
                    mma16816(c0[0], c0[1], c0[2], c0[3],
                             ah0, ah1, ah2, ah3, bh[p][0], bh[p][2]);
                    mma16816(c0[0], c0[1], c0[2], c0[3],
                             al0, al1, al2, al3, bh[p][0], bh[p][2]);
                    mma16816(c0[0], c0[1], c0[2], c0[3],
                             ah0, ah1, ah2, ah3, bl[p][0], bl[p][2]);
                    float* c1 = acc[mt][p * 2 + 1];
                    mma16816(c1[0], c1[1], c1[2], c1[3],
                             ah0, ah1, ah2, ah3, bh[p][1], bh[p][3]);
                    mma16816(c1[0], c1[1], c1[2], c1[3],
                             al0, al1, al2, al3, bh[p][1], bh[p][3]);
                    mma16816(c1[0], c1[1], c1[2], c1[3],
                             ah0, ah1, ah2, ah3, bl[p][1], bl[p][3]);
                }
            }
        }
        __syncthreads();
        if (it + 1 < NIT) {
            STORE_TILE();
            __syncthreads();
        }
    }

#pragma unroll
    for (int mt = 0; mt < 4; mt++) {
#pragma unroll
        for (int nt = 0; nt < 4; nt++) {
            int gr = bm + wm + mt * 16 + (lane >> 2);
            int gc = bn + wn + nt * 8 + (lane & 3) * 2;
            float* c = acc[mt][nt];
            *(float2*)(C + (size_t)gr * N + gc)       = make_float2(c[0], c[1]);
            *(float2*)(C + (size_t)(gr + 8) * N + gc) = make_float2(c[2], c[3]);
        }
    }
#undef LOAD_TILE
#undef STORE_TILE
}

// ---------------------------------------------------------------------------
// Tensor-core flash attention (split-bf16).
// grid = (S/128, B*H), block = 256 (8 warps x 16 query rows).
// BC = 64 keys per iteration. K/V tiles in smem as bf16 hi+lo, padded
// stride 72 (144 B = 9*16 B: ldmatrix-aligned, conflict-free).
// ---------------------------------------------------------------------------
#define FSTR 72

__global__ __launch_bounds__(256) void flash_attn_tc(const float* __restrict__ Qp,
                                                     const float* __restrict__ Kp,
                                                     const float* __restrict__ Vp,
                                                     float* __restrict__ Op)
{
    __shared__ __align__(16) __nv_bfloat16 sKh[64][FSTR];
    __shared__ __align__(16) __nv_bfloat16 sKl[64][FSTR];
    __shared__ __align__(16) __nv_bfloat16 sVh[64][FSTR];
    __shared__ __align__(16) __nv_bfloat16 sVl[64][FSTR];

    const int tid  = threadIdx.x;
    const int lane = tid & 31;
    const int wid  = tid >> 5;
    const int g    = lane >> 2;        // group id (row within warp strip)
    const int q2   = (lane & 3) * 2;   // col pair base

    const int bh = blockIdx.y;
    const int b = bh >> 4;
    const int h = bh & 15;

    const int lrow = lane & 15;
    const int lcol = (lane >> 4) << 3;

    uint32_t base_Kh = (uint32_t)__cvta_generic_to_shared(&sKh[0][0]);
    uint32_t base_Kl = (uint32_t)__cvta_generic_to_shared(&sKl[0][0]);
    uint32_t base_Vh = (uint32_t)__cvta_generic_to_shared(&sVh[0][0]);
    uint32_t base_Vl = (uint32_t)__cvta_generic_to_shared(&sVl[0][0]);

    // ---- Q fragments (scaled by 1/8), register-resident: 4 k-steps, hi+lo
    uint32_t Qh[4][4], Ql[4][4];
    {
        const int r0 = b * S_LEN + blockIdx.x * 128 + wid * 16 + g;
        const float* q0 = Qp + (size_t)r0 * EMB + h * DK;
        const float* q1 = q0 + (size_t)8 * EMB;
#pragma unroll
        for (int s = 0; s < 4; s++) {
#pragma unroll
            for (int half = 0; half < 2; half++) {
                float2 u0 = *(const float2*)(q0 + s * 16 + half * 8 + q2);
                float2 u1 = *(const float2*)(q1 + s * 16 + half * 8 + q2);
                u0.x *= 0.125f; u0.y *= 0.125f;
                u1.x *= 0.125f; u1.y *= 0.125f;
                float h00 = __bfloat162float(__float2bfloat16_rn(u0.x));
                float h01 = __bfloat162float(__float2bfloat16_rn(u0.y));
                float h10 = __bfloat162float(__float2bfloat16_rn(u1.x));
                float h11 = __bfloat162float(__float2bfloat16_rn(u1.y));
                Qh[s][half * 2 + 0] = pack2(u0.x, u0.y);
                Qh[s][half * 2 + 1] = pack2(u1.x, u1.y);
                Ql[s][half * 2 + 0] = pack2(u0.x - h00, u0.y - h01);
                Ql[s][half * 2 + 1] = pack2(u1.x - h10, u1.y - h11);
            }
        }
    }

    float oacc[8][4];
#pragma unroll
    for (int i = 0; i < 8; i++)
#pragma unroll
        for (int c = 0; c < 4; c++) oacc[i][c] = 0.f;
    float m0 = -1e30f, m1 = -1e30f, l0 = 0.f, l1 = 0.f;

    const float* Kbase = Kp + (size_t)(b * S_LEN) * EMB + h * DK;
    const float* Vbase = Vp + (size_t)(b * S_LEN) * EMB + h * DK;

    float4 pk[4], pv[4];

    // thread -> (row, col4) for tile loads: 64 rows x 16 float4
#define FA_LOAD(t0)                                                            \
    {                                                                          \
        _Pragma("unroll")                                                      \
        for (int i = 0; i < 4; i++) {                                          \
            int v = tid + (i << 8);                                            \
            int r = v >> 4, c4 = (v & 15) << 2;                                \
            pk[i] = *(const float4*)(Kbase + (size_t)((t0) + r) * EMB + c4);   \
            pv[i] = *(const float4*)(Vbase + (size_t)((t0) + r) * EMB + c4);   \
        }                                                                      \
    }

#define FA_STORE()                                                             \
    {                                                                          \
        _Pragma("unroll")                                                      \
        for (int i = 0; i < 4; i++) {                                          \
            int v = tid + (i << 8);                                            \
            int r = v >> 4, c4 = (v & 15) << 2;                                \
            float4 f = pk[i];                                                  \
            float h0 = __bfloat162float(__float2bfloat16_rn(f.x));             \
            float h1 = __bfloat162float(__float2bfloat16_rn(f.y));             \
            float h2 = __bfloat162float(__float2bfloat16_rn(f.z));             \
            float h3 = __bfloat162float(__float2bfloat16_rn(f.w));             \
            *(uint2*)&sKh[r][c4] = make_uint2(pack2(f.x, f.y), pack2(f.z, f.w));\
            *(uint2*)&sKl[r][c4] = make_uint2(pack2(f.x - h0, f.y - h1),       \
                                              pack2(f.z - h2, f.w - h3));      \
            f = pv[i];                                                         \
            h0 = __bfloat162float(__float2bfloat16_rn(f.x));                   \
            h1 = __bfloat162float(__float2bfloat16_rn(f.y));                   \
            h2 = __bfloat162float(__float2bfloat16_rn(f.z));                   \
            h3 = __bfloat162float(__float2bfloat16_rn(f.w));                   \
            *(uint2*)&sVh[r][c4] = make_uint2(pack2(f.x, f.y), pack2(f.z, f.w));\
            *(uint2*)&sVl[r][c4] = make_uint2(pack2(f.x - h0, f.y - h1),       \
                                              pack2(f.z - h2, f.w - h3));      \
        }                                                                      \
    }

    FA_LOAD(0);
    FA_STORE();
    __syncthreads();

    const int NIT = S_LEN / 64;  // 32
    for (int it = 0; it < NIT; it++) {
        if (it + 1 < NIT) FA_LOAD((it + 1) * 64);

        // ---- scores S[16 x 64] in fragments: 8 n8-tiles x 4
        float sacc[8][4];
#pragma unroll
        for (int i = 0; i < 8; i++)
#pragma unroll
            for (int c = 0; c < 4; c++) sacc[i][c] = 0.f;

#pragma unroll
        for (int np = 0; np < 4; np++) {
#pragma unroll
            for (int s = 0; s < 4; s++) {
                uint32_t off = (uint32_t)((np * 16 + lrow) * FSTR + s * 16 + lcol) * 2;
                uint32_t kh0, kh1, kh2, kh3, kl0, kl1, kl2, kl3;
                ldm_x4(kh0, kh1, kh2, kh3, base_Kh + off);
                ldm_x4(kl0, kl1, kl2, kl3, base_Kl + off);
                float* c0 = sacc[np * 2];
                mma16816(c0[0], c0[1], c0[2], c0[3],
                         Qh[s][0], Qh[s][1], Qh[s][2], Qh[s][3], kh0, kh2);
                mma16816(c0[0], c0[1], c0[2], c0[3],
                         Ql[s][0], Ql[s][1], Ql[s][2], Ql[s][3], kh0, kh2);
                mma16816(c0[0], c0[1], c0[2], c0[3],
                         Qh[s][0], Qh[s][1], Qh[s][2], Qh[s][3], kl0, kl2);
                float* c1 = sacc[np * 2 + 1];
                mma16816(c1[0], c1[1], c1[2], c1[3],
                         Qh[s][0], Qh[s][1], Qh[s][2], Qh[s][3], kh1, kh3);
                mma16816(c1[0], c1[1], c1[2], c1[3],
                         Ql[s][0], Ql[s][1], Ql[s][2], Ql[s][3], kh1, kh3);
                mma16816(c1[0], c1[1], c1[2], c1[3],
                         Qh[s][0], Qh[s][1], Qh[s][2], Qh[s][3], kl1, kl3);
            }
        }

        // ---- online softmax on fragments
        float tm0 = -1e30f, tm1 = -1e30f;
#pragma unroll
        for (int i = 0; i < 8; i++) {
            tm0 = fmaxf(tm0, fmaxf(sacc[i][0], sacc[i][1]));
            tm1 = fmaxf(tm1, fmaxf(sacc[i][2], sacc[i][3]));
        }
        tm0 = fmaxf(tm0, __shfl_xor_sync(0xffffffffu, tm0, 1));
        tm0 = fmaxf(tm0, __shfl_xor_sync(0xffffffffu, tm0, 2));
        tm1 = fmaxf(tm1, __shfl_xor_sync(0xffffffffu, tm1, 1));
        tm1 = fmaxf(tm1, __shfl_xor_sync(0xffffffffu, tm1, 2));

        float mn0 = fmaxf(m0, tm0);
        float mn1 = fmaxf(m1, tm1);
        float cr0 = __expf(m0 - mn0);
        float cr1 = __expf(m1 - mn1);
        m0 = mn0; m1 = mn1;
        l0 *= cr0; l1 *= cr1;
#pragma unroll
        for (int i = 0; i < 8; i++) {
            oacc[i][0] *= cr0; oacc[i][1] *= cr0;
            oacc[i][2] *= cr1; oacc[i][3] *= cr1;
        }

        // exp -> P (overwrite sacc), accumulate row sums
#pragma unroll
        for (int i = 0; i < 8; i++) {
            float p0 = __expf(sacc[i][0] - mn0);
            float p1 = __expf(sacc[i][1] - mn0);
            float p2 = __expf(sacc[i][2] - mn1);
            float p3 = __expf(sacc[i][3] - mn1);
            sacc[i][0] = p0; sacc[i][1] = p1; sacc[i][2] = p2; sacc[i][3] = p3;
            l0 += p0 + p1; l1 += p2 + p3;
        }

        // ---- PV: O += P * V
#pragma unroll
        for (int ks = 0; ks < 4; ks++) {
            // A-fragments from score tiles 2ks, 2ks+1 (hi + lo)
            float* pA = sacc[2 * ks];
            float* pB = sacc[2 * ks + 1];
            float hA0 = __bfloat162float(__float2bfloat16_rn(pA[0]));
            float hA1 = __bfloat162float(__float2bfloat16_rn(pA[1]));
            float hA2 = __bfloat162float(__float2bfloat16_rn(pA[2]));
            float hA3 = __bfloat162float(__float2bfloat16_rn(pA[3]));
            float hB0 = __bfloat162float(__float2bfloat16_rn(pB[0]));
            float hB1 = __bfloat162float(__float2bfloat16_rn(pB[1]));
            float hB2 = __bfloat162float(__float2bfloat16_rn(pB[2]));
            float hB3 = __bfloat162float(__float2bfloat16_rn(pB[3]));
            uint32_t ah0 = pack2(pA[0], pA[1]);
            uint32_t ah1 = pack2(pA[2], pA[3]);
            uint32_t ah2 = pack2(pB[0], pB[1]);
            uint32_t ah3 = pack2(pB[2], pB[3]);
            uint32_t al0 = pack2(pA[0] - hA0, pA[1] - hA1);
            uint32_t al1 = pack2(pA[2] - hA2, pA[3] - hA3);
            uint32_t al2 = pack2(pB[0] - hB0, pB[1] - hB1);
            uint32_t al3 = pack2(pB[2] - hB2, pB[3] - hB3);

#pragma unroll
            for (int np = 0; np < 4; np++) {
                uint32_t off = (uint32_t)((ks * 16 + lrow) * FSTR + np * 16 + lcol) * 2;
                uint32_t vh0, vh1, vh2, vh3, vl0, vl1, vl2, vl3;
                ldm_x4_t(vh0, vh1, vh2, vh3, base_Vh + off);
                ldm_x4_t(vl0, vl1, vl2, vl3, base_Vl + off);
                float* c0 = oacc[np * 2];
                mma16816(c0[0], c0[1], c0[2], c0[3],
                         ah0, ah1, ah2, ah3, vh0, vh1);
                mma16816(c0[0], c0[1], c0[2], c0[3],
                         al0, al1, al2, al3, vh0, vh1);
                mma16816(c0[0], c0[1], c0[2], c0[3],
                         ah0, ah1, ah2, ah3, vl0, vl1);
                float* c1 = oacc[np * 2 + 1];
                mma16816(c1[0], c1[1], c1[2], c1[3],
                         ah0, ah1, ah2, ah3, vh2, vh3);
                mma16816(c1[0], c1[1], c1[2], c1[3],
                         al0, al1, al2, al3, vh2, vh3);
                mma16816(c1[0], c1[1], c1[2], c1[3],
                         ah0, ah1, ah2, ah3, vl2, vl3);
            }
        }

        __syncthreads();
        if (it + 1 < NIT) {
            FA_STORE();
            __syncthreads();
        }
    }

    // ---- finalize: reduce l across quad, normalize, write
    l0 += __shfl_xor_sync(0xffffffffu, l0, 1);
    l0 += __shfl_xor_sync(0xffffffffu, l0, 2);
    l1 += __shfl_xor_sync(0xffffffffu, l1, 1);
    l1 += __shfl_xor_sync(0xffffffffu, l1, 2);
    float inv0 = 1.0f / l0;
    float inv1 = 1.0f / l1;

    const int r0 = b * S_LEN + blockIdx.x * 128 + wid * 16 + g;
    float* o0 = Op + (size_t)r0 * EMB + h * DK;
    float* o1 = o0 + (size_t)8 * EMB;
#pragma unroll
    for (int nt = 0; nt < 8; nt++) {
        int n = nt * 8 + q2;
        *(float2*)(o0 + n) = make_float2(oacc[nt][0] * inv0, oacc[nt][1] * inv0);
        *(float2*)(o1 + n) = make_float2(oacc[nt][2] * inv1, oacc[nt][3] * inv1);
    }
#undef FA_LOAD
#undef FA_STORE
}

// ---------------------------------------------------------------------------
extern "C" void kernel_launch(void* const* d_in, const int* in_sizes, int n_in,
                              void* d_out, int out_size)
{
    (void)in_sizes; (void)n_in; (void)out_size;
    const float* Q  = (const float*)d_in[0];
    const float* Kx = (const float*)d_in[1];
    const float* V  = (const float*)d_in[2];
    // d_in[3] = mask (unused)
    const float* Wq = (const float*)d_in[4];
    const float* Wk = (const float*)d_in[5];
    const float* Wv = (const float*)d_in[6];
    const float* Wo = (const float*)d_in[7];
    float* out = (float*)d_out;

    float *gq, *gk, *gv, *gctx;
    cudaGetSymbolAddress((void**)&gq,   g_q);
    cudaGetSymbolAddress((void**)&gk,   g_k);
    cudaGetSymbolAddress((void**)&gv,   g_v);
    cudaGetSymbolAddress((void**)&gctx, g_ctx);

    dim3 gg(EMB / BN, MTOT / BM);     // (8, 64)
    gemm_nt_tc<<<gg, 256>>>(Q,  Wq, gq);
    gemm_nt_tc<<<gg, 256>>>(Kx, Wk, gk);
    gemm_nt_tc<<<gg, 256>>>(V,  Wv, gv);

    dim3 ga(S_LEN / 128, BATCH * NH); // (16, 64)
    flash_attn_tc<<<ga, 256>>>(gq, gk, gv, gctx);

    gemm_nt_tc<<<gg, 256>>>(gctx, Wo, out);
}

// round 4
// speedup vs baseline: 2.7596x; 1.0108x over previous
#include <cuda_runtime.h>
#include <cuda_bf16.h>
#include <cstdint>

#define S_LEN 2048
#define BATCH 4
#define EMB   1024
#define NH    16
#define DK    64
#define MTOT  (BATCH * S_LEN)   // 8192

typedef __nv_bfloat16 bf16;

// ---- global scratch (no allocations allowed) ------------------------------
__device__ bf16 g_xh[3][MTOT * EMB], g_xl[3][MTOT * EMB];   // split inputs Q,K,V
__device__ bf16 g_wh[4][EMB * EMB],  g_wl[4][EMB * EMB];    // split weights
__device__ bf16 g_ph[3][MTOT * EMB], g_pl[3][MTOT * EMB];   // split projections q,k,v
__device__ bf16 g_ch[MTOT * EMB],    g_cl[MTOT * EMB];      // split attention ctx

__device__ __forceinline__ uint32_t pack2(float a, float b) {
    __nv_bfloat162 t = __floats2bfloat162_rn(a, b);
    return *reinterpret_cast<uint32_t*>(&t);
}

__device__ __forceinline__ void ldm_x4(uint32_t& r0, uint32_t& r1,
                                       uint32_t& r2, uint32_t& r3, uint32_t addr) {
    asm volatile("ldmatrix.sync.aligned.m8n8.x4.shared.b16 {%0,%1,%2,%3}, [%4];"
                 : "=r"(r0), "=r"(r1), "=r"(r2), "=r"(r3) : "r"(addr));
}
__device__ __forceinline__ void ldm_x4_t(uint32_t& r0, uint32_t& r1,
                                         uint32_t& r2, uint32_t& r3, uint32_t addr) {
    asm volatile("ldmatrix.sync.aligned.m8n8.x4.trans.shared.b16 {%0,%1,%2,%3}, [%4];"
                 : "=r"(r0), "=r"(r1), "=r"(r2), "=r"(r3) : "r"(addr));
}
__device__ __forceinline__ void mma16816(float& c0, float& c1, float& c2, float& c3,
                                         uint32_t a0, uint32_t a1, uint32_t a2, uint32_t a3,
                                         uint32_t b0, uint32_t b1) {
    asm volatile("mma.sync.aligned.m16n8k16.row.col.f32.bf16.bf16.f32 "
                 "{%0,%1,%2,%3},{%4,%5,%6,%7},{%8,%9},{%0,%1,%2,%3};"
                 : "+f"(c0), "+f"(c1), "+f"(c2), "+f"(c3)
                 : "r"(a0), "r"(a1), "r"(a2), "r"(a3), "r"(b0), "r"(b1));
}
__device__ __forceinline__ void cp16(uint32_t saddr, const void* gaddr) {
    asm volatile("cp.async.cg.shared.global [%0], [%1], 16;" :: "r"(saddr), "l"(gaddr));
}
__device__ __forceinline__ void cp_commit() { asm volatile("cp.async.commit_group;"); }
template <int N>
__device__ __forceinline__ void cp_wait() { asm volatile("cp.async.wait_group %0;" :: "n"(N)); }

// ---------------------------------------------------------------------------
// split: fp32 -> (hi, lo) bf16 planes
// ---------------------------------------------------------------------------
__global__ __launch_bounds__(256) void split_f32(const float* __restrict__ X,
                                                 bf16* __restrict__ Xh,
                                                 bf16* __restrict__ Xl, int n4)
{
    int i = blockIdx.x * blockDim.x + threadIdx.x;
    if (i >= n4) return;
    float4 f = ((const float4*)X)[i];
    float h0 = __bfloat162float(__float2bfloat16_rn(f.x));
    float h1 = __bfloat162float(__float2bfloat16_rn(f.y));
    float h2 = __bfloat162float(__float2bfloat16_rn(f.z));
    float h3 = __bfloat162float(__float2bfloat16_rn(f.w));
    ((uint2*)Xh)[i] = make_uint2(pack2(f.x, f.y), pack2(f.z, f.w));
    ((uint2*)Xl)[i] = make_uint2(pack2(f.x - h0, f.y - h1), pack2(f.z - h2, f.w - h3));
}

// ---------------------------------------------------------------------------
// Split-bf16 GEMM on pre-split planes:  C = A * B^T  (A[M,K], B[N,K])
// MODE 0: write fp32 C.   MODE 1: write hi/lo bf16 planes Ch, Cl.
// 128x128x32 tile, 256 thr, cp.async double-buffered dynamic smem (80 KB).
// ---------------------------------------------------------------------------
#define SSTR 40
#define GSTG 40960u      // bytes per stage (4 planes * 128 * SSTR * 2)
#define GPL  10240u      // bytes per plane

template <int MODE>
__global__ __launch_bounds__(256) void gemm_nt_split(
    const bf16* __restrict__ Ah, const bf16* __restrict__ Al,
    const bf16* __restrict__ Bh, const bf16* __restrict__ Bl,
    float* __restrict__ C, bf16* __restrict__ Ch, bf16* __restrict__ Cl)
{
    const int K = EMB, N = EMB;
    extern __shared__ bf16 smem[];
    uint32_t sbase = (uint32_t)__cvta_generic_to_shared(smem);

    const int tid  = threadIdx.x;
    const int lane = tid & 31;
    const int wid  = tid >> 5;
    const int wm = (wid & 1) * 64;
    const int wn = (wid >> 1) * 32;
    const int bm = blockIdx.y * 128;
    const int bn = blockIdx.x * 128;

    const bf16* Aph = Ah + (size_t)bm * K;
    const bf16* Apl = Al + (size_t)bm * K;
    const bf16* Bph = Bh + (size_t)bn * K;
    const bf16* Bpl = Bl + (size_t)bn * K;

    const int cr = tid >> 2;          // 0..63
    const int cc = (tid & 3) * 8;     // 0,8,16,24

    const int lrow = lane & 15;
    const int lcol = (lane >> 4) << 3;

    float acc[4][4][4];
#pragma unroll
    for (int i = 0; i < 4; i++)
#pragma unroll
        for (int j = 0; j < 4; j++)
#pragma unroll
            for (int c = 0; c < 4; c++) acc[i][j][c] = 0.f;

#define GISSUE(k0, stg) {                                                      \
        uint32_t sb = sbase + (uint32_t)(stg) * GSTG;                          \
        size_t go1 = (size_t)cr * K + (size_t)(k0) + cc;                       \
        size_t go2 = (size_t)(cr + 64) * K + (size_t)(k0) + cc;                \
        uint32_t so1 = (uint32_t)(cr * SSTR + cc) * 2u;                        \
        uint32_t so2 = (uint32_t)((cr + 64) * SSTR + cc) * 2u;                 \
        cp16(sb + so1,            Aph + go1);                                  \
        cp16(sb + so2,            Aph + go2);                                  \
        cp16(sb + GPL + so1,      Apl + go1);                                  \
        cp16(sb + GPL + so2,      Apl + go2);                                  \
        cp16(sb + 2 * GPL + so1,  Bph + go1);                                  \
        cp16(sb + 2 * GPL + so2,  Bph + go2);                                  \
        cp16(sb + 3 * GPL + so1,  Bpl + go1);                                  \
        cp16(sb + 3 * GPL + so2,  Bpl + go2);                                  \
    }

    GISSUE(0, 0); cp_commit();

    const int NIT = K / 32;  // 32
    for (int it = 0; it < NIT; it++) {
        const int s = it & 1;
        if (it + 1 < NIT) { GISSUE((it + 1) * 32, s ^ 1); cp_commit(); cp_wait<1>(); }
        else              { cp_wait<0>(); }
        __syncthreads();

        uint32_t bAh = sbase + (uint32_t)s * GSTG;
        uint32_t bAl = bAh + GPL;
        uint32_t bBh = bAh + 2 * GPL;
        uint32_t bBl = bAh + 3 * GPL;

#pragma unroll
        for (int ks = 0; ks < 32; ks += 16) {
            uint32_t bh[2][4], bl[2][4];
#pragma unroll
            for (int p = 0; p < 2; p++) {
                uint32_t off = (uint32_t)((wn + p * 16 + lrow) * SSTR + ks + lcol) * 2;
                ldm_x4(bh[p][0], bh[p][1], bh[p][2], bh[p][3], bBh + off);
                ldm_x4(bl[p][0], bl[p][1], bl[p][2], bl[p][3], bBl + off);
            }
#pragma unroll
            for (int mt = 0; mt < 4; mt++) {
                uint32_t off = (uint32_t)((wm + mt * 16 + lrow) * SSTR + ks + lcol) * 2;
                uint32_t ah0, ah1, ah2, ah3, al0, al1, al2, al3;
                ldm_x4(ah0, ah1, ah2, ah3, bAh + off);
                ldm_x4(al0, al1, al2, al3, bAl + off);
#pragma unroll
                for (int p = 0; p < 2; p++) {
                    float* c0 = acc[mt][p * 2];
                    mma16816(c0[0], c0[1], c0[2], c0[3],
                             ah0, ah1, ah2, ah3, bh[p][0], bh[p][2]);
                    mma16816(c0[0], c0[1], c0[2], c0[3],
                             al0, al1, al2, al3, bh[p][0], bh[p][2]);
                    mma16816(c0[0], c0[1], c0[2], c0[3],
                             ah0, ah1, ah2, ah3, bl[p][0], bl[p][2]);
                    float* c1 = acc[mt][p * 2 + 1];
                    mma16816(c1[0], c1[1], c1[2], c1[3],
                             ah0, ah1, ah2, ah3, bh[p][1], bh[p][3]);
                    mma16816(c1[0], c1[1], c1[2], c1[3],
                             al0, al1, al2, al3, bh[p][1], bh[p][3]);
                    mma16816(c1[0], c1[1], c1[2], c1[3],
                             ah0, ah1, ah2, ah3, bl[p][1], bl[p][3]);
                }
            }
        }
        __syncthreads();
    }

#pragma unroll
    for (int mt = 0; mt < 4; mt++) {
#pragma unroll
        for (int nt = 0; nt < 4; nt++) {
            int gr = bm + wm + mt * 16 + (lane >> 2);
            int gc = bn + wn + nt * 8 + (lane & 3) * 2;
            float* c = acc[mt][nt];
            if (MODE == 0) {
                *(float2*)(C + (size_t)gr * N + gc)       = make_float2(c[0], c[1]);
                *(float2*)(C + (size_t)(gr + 8) * N + gc) = make_float2(c[2], c[3]);
            } else {
                float h0 = __bfloat162float(__float2bfloat16_rn(c[0]));
                float h1 = __bfloat162float(__float2bfloat16_rn(c[1]));
                float h2 = __bfloat162float(__float2bfloat16_rn(c[2]));
                float h3 = __bfloat162float(__float2bfloat16_rn(c[3]));
                *(uint32_t*)(Ch + (size_t)gr * N + gc)       = pack2(c[0], c[1]);
                *(uint32_t*)(Cl + (size_t)gr * N + gc)       = pack2(c[0] - h0, c[1] - h1);
                *(uint32_t*)(Ch + (size_t)(gr + 8) * N + gc) = pack2(c[2], c[3]);
                *(uint32_t*)(Cl + (size_t)(gr + 8) * N + gc) = pack2(c[2] - h2, c[3] - h3);
            }
        }
    }
#undef GISSUE
}

// ---------------------------------------------------------------------------
// Tensor-core flash attention on pre-split planes (cp.async double-buffered).
// grid = (S/128, B*H), block = 256. BC=64. Dynamic smem 72 KB.
// ---------------------------------------------------------------------------
#define FSTR 72
#define FSTG 36864u
#define FPL  9216u

__global__ __launch_bounds__(256) void flash_attn_tc2(
    const bf16* __restrict__ qh, const bf16* __restrict__ ql,
    const bf16* __restrict__ kh, const bf16* __restrict__ kl,
    const bf16* __restrict__ vh, const bf16* __restrict__ vl,
    bf16* __restrict__ ch, bf16* __restrict__ cl)
{
    extern __shared__ bf16 fsmem[];
    uint32_t fsbase = (uint32_t)__cvta_generic_to_shared(fsmem);

    const int tid  = threadIdx.x;
    const int lane = tid & 31;
    const int wid  = tid >> 5;
    const int g    = lane >> 2;
    const int q2   = (lane & 3) * 2;

    const int bh_ = blockIdx.y;
    const int b = bh_ >> 4;
    const int h = bh_ & 15;

    const int lrow = lane & 15;
    const int lcol = (lane >> 4) << 3;

    const bf16* Khp = kh + (size_t)(b * S_LEN) * EMB + h * DK;
    const bf16* Klp = kl + (size_t)(b * S_LEN) * EMB + h * DK;
    const bf16* Vhp = vh + (size_t)(b * S_LEN) * EMB + h * DK;
    const bf16* Vlp = vl + (size_t)(b * S_LEN) * EMB + h * DK;

    const int fr = tid >> 3;        // 0..31
    const int fc = (tid & 7) * 8;   // 0..56

    // ---- Q fragments (hi/lo bf16, scaled by exact 1/8)
    uint32_t Qh[4][4], Ql[4][4];
    {
        const int r0 = b * S_LEN + blockIdx.x * 128 + wid * 16 + g;
        const bf16* q0h = qh + (size_t)r0 * EMB + h * DK;
        const bf16* q0l = ql + (size_t)r0 * EMB + h * DK;
        const __nv_bfloat162 sc = __floats2bfloat162_rn(0.125f, 0.125f);
#pragma unroll
        for (int s = 0; s < 4; s++) {
#pragma unroll
            for (int half = 0; half < 2; half++) {
                int c = s * 16 + half * 8 + q2;
                __nv_bfloat162 t;
                t = __hmul2(*(const __nv_bfloat162*)(q0h + c), sc);
                Qh[s][half * 2 + 0] = *(uint32_t*)&t;
                t = __hmul2(*(const __nv_bfloat162*)(q0h + 8 * EMB + c), sc);
                Qh[s][half * 2 + 1] = *(uint32_t*)&t;
                t = __hmul2(*(const __nv_bfloat162*)(q0l + c), sc);
                Ql[s][half * 2 + 0] = *(uint32_t*)&t;
                t = __hmul2(*(const __nv_bfloat162*)(q0l + 8 * EMB + c), sc);
                Ql[s][half * 2 + 1] = *(uint32_t*)&t;
            }
        }
    }

    float oacc[8][4];
#pragma unroll
    for (int i = 0; i < 8; i++)
#pragma unroll
        for (int c = 0; c < 4; c++) oacc[i][c] = 0.f;
    float m0 = -1e30f, m1 = -1e30f, l0 = 0.f, l1 = 0.f;

#define FISSUE(t0, stg) {                                                      \
        uint32_t sb = fsbase + (uint32_t)(stg) * FSTG;                         \
        size_t go1 = (size_t)((t0) + fr) * EMB + fc;                           \
        size_t go2 = (size_t)((t0) + fr + 32) * EMB + fc;                      \
        uint32_t so1 = (uint32_t)(fr * FSTR + fc) * 2u;                        \
        uint32_t so2 = (uint32_t)((fr + 32) * FSTR + fc) * 2u;                 \
        cp16(sb + so1,           Khp + go1);                                   \
        cp16(sb + so2,           Khp + go2);                                   \
        cp16(sb + FPL + so1,     Klp + go1);                                   \
        cp16(sb + FPL + so2,     Klp + go2);                                   \
        cp16(sb + 2 * FPL + so1, Vhp + go1);                                   \
        cp16(sb + 2 * FPL + so2, Vhp + go2);                                   \
        cp16(sb + 3 * FPL + so1, Vlp + go1);                                   \
        cp16(sb + 3 * FPL + so2, Vlp + go2);                                   \
    }

    FISSUE(0, 0); cp_commit();

    const int NIT = S_LEN / 64;  // 32
    for (int it = 0; it < NIT; it++) {
        const int s = it & 1;
        if (it + 1 < NIT) { FISSUE((it + 1) * 64, s ^ 1); cp_commit(); cp_wait<1>(); }
        else              { cp_wait<0>(); }
        __syncthreads();

        uint32_t bKh = fsbase + (uint32_t)s * FSTG;
        uint32_t bKl = bKh + FPL;
        uint32_t bVh = bKh + 2 * FPL;
        uint32_t bVl = bKh + 3 * FPL;

        // ---- scores
        float sacc[8][4];
#pragma unroll
        for (int i = 0; i < 8; i++)
#pragma unroll
            for (int c = 0; c < 4; c++) sacc[i][c] = 0.f;

#pragma unroll
        for (int np = 0; np < 4; np++) {
#pragma unroll
            for (int sk = 0; sk < 4; sk++) {
                uint32_t off = (uint32_t)((np * 16 + lrow) * FSTR + sk * 16 + lcol) * 2;
                uint32_t kh0, kh1, kh2, kh3, kl0, kl1, kl2, kl3;
                ldm_x4(kh0, kh1, kh2, kh3, bKh + off);
                ldm_x4(kl0, kl1, kl2, kl3, bKl + off);
                float* c0 = sacc[np * 2];
                mma16816(c0[0], c0[1], c0[2], c0[3],
                         Qh[sk][0], Qh[sk][1], Qh[sk][2], Qh[sk][3], kh0, kh2);
                mma16816(c0[0], c0[1], c0[2], c0[3],
                         Ql[sk][0], Ql[sk][1], Ql[sk][2], Ql[sk][3], kh0, kh2);
                mma16816(c0[0], c0[1], c0[2], c0[3],
                         Qh[sk][0], Qh[sk][1], Qh[sk][2], Qh[sk][3], kl0, kl2);
                float* c1 = sacc[np * 2 + 1];
                mma16816(c1[0], c1[1], c1[2], c1[3],
                         Qh[sk][0], Qh[sk][1], Qh[sk][2], Qh[sk][3], kh1, kh3);
                mma16816(c1[0], c1[1], c1[2], c1[3],
                         Ql[sk][0], Ql[sk][1], Ql[sk][2], Ql[sk][3], kh1, kh3);
                mma16816(c1[0], c1[1], c1[2], c1[3],
                         Qh[sk][0], Qh[sk][1], Qh[sk][2], Qh[sk][3], kl1, kl3);
            }
        }

        // ---- online softmax
        float tm0 = -1e30f, tm1 = -1e30f;
#pragma unroll
        for (int i = 0; i < 8; i++) {
            tm0 = fmaxf(tm0, fmaxf(sacc[i][0], sacc[i][1]));
            tm1 = fmaxf(tm1, fmaxf(sacc[i][2], sacc[i][3]));
        }
        tm0 = fmaxf(tm0, __shfl_xor_sync(0xffffffffu, tm0, 1));
        tm0 = fmaxf(tm0, __shfl_xor_sync(0xffffffffu, tm0, 2));
        tm1 = fmaxf(tm1, __shfl_xor_sync(0xffffffffu, tm1, 1));
        tm1 = fmaxf(tm1, __shfl_xor_sync(0xffffffffu, tm1, 2));

        float mn0 = fmaxf(m0, tm0);
        float mn1 = fmaxf(m1, tm1);
        float cr0 = __expf(m0 - mn0);
        float cr1 = __expf(m1 - mn1);
        m0 = mn0; m1 = mn1;
        l0 *= cr0; l1 *= cr1;
#pragma unroll
        for (int i = 0; i < 8; i++) {
            oacc[i][0] *= cr0; oacc[i][1] *= cr0;
            oacc[i][2] *= cr1; oacc[i][3] *= cr1;
        }
#pragma unroll
        for (int i = 0; i < 8; i++) {
            float p0 = __expf(sacc[i][0] - mn0);
            float p1 = __expf(sacc[i][1] - mn0);
            float p2 = __expf(sacc[i][2] - mn1);
            float p3 = __expf(sacc[i][3] - mn1);
            sacc[i][0] = p0; sacc[i][1] = p1; sacc[i][2] = p2; sacc[i][3] = p3;
            l0 += p0 + p1; l1 += p2 + p3;
        }

        // ---- PV
#pragma unroll
        for (int ks = 0; ks < 4; ks++) {
            float* pA = sacc[2 * ks];
            float* pB = sacc[2 * ks + 1];
            float hA0 = __bfloat162float(__float2bfloat16_rn(pA[0]));
            float hA1 = __bfloat162float(__float2bfloat16_rn(pA[1]));
            float hA2 = __bfloat162float(__float2bfloat16_rn(pA[2]));
            float hA3 = __bfloat162float(__float2bfloat16_rn(pA[3]));
            float hB0 = __bfloat162float(__float2bfloat16_rn(pB[0]));
            float hB1 = __bfloat162float(__float2bfloat16_rn(pB[1]));
            float hB2 = __bfloat162float(__float2bfloat16_rn(pB[2]));
            float hB3 = __bfloat162float(__float2bfloat16_rn(pB[3]));
            uint32_t ah0 = pack2(pA[0], pA[1]);
            uint32_t ah1 = pack2(pA[2], pA[3]);
            uint32_t ah2 = pack2(pB[0], pB[1]);
            uint32_t ah3 = pack2(pB[2], pB[3]);
            uint32_t al0 = pack2(pA[0] - hA0, pA[1] - hA1);
            uint32_t al1 = pack2(pA[2] - hA2, pA[3] - hA3);
            uint32_t al2 = pack2(pB[0] - hB0, pB[1] - hB1);
            uint32_t al3 = pack2(pB[2] - hB2, pB[3] - hB3);

#pragma unroll
            for (int np = 0; np < 4; np++) {
                uint32_t off = (uint32_t)((ks * 16 + lrow) * FSTR + np * 16 + lcol) * 2;
                uint32_t vh0, vh1, vh2, vh3, vl0, vl1, vl2, vl3;
                ldm_x4_t(vh0, vh1, vh2, vh3, bVh + off);
                ldm_x4_t(vl0, vl1, vl2, vl3, bVl + off);
                float* c0 = oacc[np * 2];
                mma16816(c0[0], c0[1], c0[2], c0[3], ah0, ah1, ah2, ah3, vh0, vh1);
                mma16816(c0[0], c0[1], c0[2], c0[3], al0, al1, al2, al3, vh0, vh1);
                mma16816(c0[0], c0[1], c0[2], c0[3], ah0, ah1, ah2, ah3, vl0, vl1);
                float* c1 = oacc[np * 2 + 1];
                mma16816(c1[0], c1[1], c1[2], c1[3], ah0, ah1, ah2, ah3, vh2, vh3);
                mma16816(c1[0], c1[1], c1[2], c1[3], al0, al1, al2, al3, vh2, vh3);
                mma16816(c1[0], c1[1], c1[2], c1[3], ah0, ah1, ah2, ah3, vl2, vl3);
            }
        }
        __syncthreads();
    }

    // ---- finalize -> ctx hi/lo planes
    l0 += __shfl_xor_sync(0xffffffffu, l0, 1);
    l0 += __shfl_xor_sync(0xffffffffu, l0, 2);
    l1 += __shfl_xor_sync(0xffffffffu, l1, 1);
    l1 += __shfl_xor_sync(0xffffffffu, l1, 2);
    float inv0 = 1.0f / l0;
    float inv1 = 1.0f / l1;

    const int r0 = b * S_LEN + blockIdx.x * 128 + wid * 16 + g;
    bf16* o0h = ch + (size_t)r0 * EMB + h * DK;
    bf16* o0l = cl + (size_t)r0 * EMB + h * DK;
#pragma unroll
    for (int nt = 0; nt < 8; nt++) {
        int n = nt * 8 + q2;
        float f0 = oacc[nt][0] * inv0, f1 = oacc[nt][1] * inv0;
        float f2 = oacc[nt][2] * inv1, f3 = oacc[nt][3] * inv1;
        float h0 = __bfloat162float(__float2bfloat16_rn(f0));
        float h1 = __bfloat162float(__float2bfloat16_rn(f1));
        float h2 = __bfloat162float(__float2bfloat16_rn(f2));
        float h3 = __bfloat162float(__float2bfloat16_rn(f3));
        *(uint32_t*)(o0h + n)           = pack2(f0, f1);
        *(uint32_t*)(o0l + n)           = pack2(f0 - h0, f1 - h1);
        *(uint32_t*)(o0h + 8 * EMB + n) = pack2(f2, f3);
        *(uint32_t*)(o0l + 8 * EMB + n) = pack2(f2 - h2, f3 - h3);
    }
#undef FISSUE
}

// ---------------------------------------------------------------------------
extern "C" void kernel_launch(void* const* d_in, const int* in_sizes, int n_in,
                              void* d_out, int out_size)
{
    (void)in_sizes; (void)n_in; (void)out_size;
    const float* IN[3] = {(const float*)d_in[0], (const float*)d_in[1], (const float*)d_in[2]};
    const float* W[4]  = {(const float*)d_in[4], (const float*)d_in[5],
                          (const float*)d_in[6], (const float*)d_in[7]};
    float* out = (float*)d_out;

    bf16 *xh, *xl, *wh, *wl, *ph, *pl, *chp, *clp;
    cudaGetSymbolAddress((void**)&xh, g_xh);
    cudaGetSymbolAddress((void**)&xl, g_xl);
    cudaGetSymbolAddress((void**)&wh, g_wh);
    cudaGetSymbolAddress((void**)&wl, g_wl);
    cudaGetSymbolAddress((void**)&ph, g_ph);
    cudaGetSymbolAddress((void**)&pl, g_pl);
    cudaGetSymbolAddress((void**)&chp, g_ch);
    cudaGetSymbolAddress((void**)&clp, g_cl);

    const int GSM = 2 * (int)GSTG;   // 81920
    const int FSM = 2 * (int)FSTG;   // 73728
    cudaFuncSetAttribute(gemm_nt_split<0>, cudaFuncAttributeMaxDynamicSharedMemorySize, GSM);
    cudaFuncSetAttribute(gemm_nt_split<1>, cudaFuncAttributeMaxDynamicSharedMemorySize, GSM);
    cudaFuncSetAttribute(flash_attn_tc2,  cudaFuncAttributeMaxDynamicSharedMemorySize, FSM);

    // split inputs and weights into bf16 hi/lo planes
    const int n4i = MTOT * EMB / 4;   // 2M
    const int n4w = EMB * EMB / 4;    // 256K
    for (int i = 0; i < 3; i++)
        split_f32<<<(n4i + 255) / 256, 256>>>(IN[i], xh + (size_t)i * MTOT * EMB,
                                              xl + (size_t)i * MTOT * EMB, n4i);
    for (int i = 0; i < 4; i++)
        split_f32<<<(n4w + 255) / 256, 256>>>(W[i], wh + (size_t)i * EMB * EMB,
                                              wl + (size_t)i * EMB * EMB, n4w);

    dim3 gg(EMB / 128, MTOT / 128);   // (8, 64)
    for (int i = 0; i < 3; i++)
        gemm_nt_split<1><<<gg, 256, GSM>>>(xh + (size_t)i * MTOT * EMB,
                                           xl + (size_t)i * MTOT * EMB,
                                           wh + (size_t)i * EMB * EMB,
                                           wl + (size_t)i * EMB * EMB,
                                           nullptr,
                                           ph + (size_t)i * MTOT * EMB,
                                           pl + (size_t)i * MTOT * EMB);

    dim3 ga(S_LEN / 128, BATCH * NH); // (16, 64)
    flash_attn_tc2<<<ga, 256, FSM>>>(ph, pl,
                                     ph + (size_t)MTOT * EMB, pl + (size_t)MTOT * EMB,
                                     ph + (size_t)2 * MTOT * EMB, pl + (size_t)2 * MTOT * EMB,
                                     chp, clp);

    gemm_nt_split<0><<<gg, 256, GSM>>>(chp, clp,
                                       wh + (size_t)3 * EMB * EMB,
                                       wl + (size_t)3 * EMB * EMB,
                                       out, nullptr, nullptr);
}

// round 6
// speedup vs baseline: 2.7787x; 1.0069x over previous
#include <cuda_runtime.h>
#include <cuda_bf16.h>
#include <cstdint>

#define S_LEN 2048
#define BATCH 4
#define EMB   1024
#define NH    16
#define DK    64
#define MTOT  (BATCH * S_LEN)   // 8192

typedef __nv_bfloat16 bf16;

// ---- global scratch (no allocations allowed) ------------------------------
__device__ bf16 g_xh[3][MTOT * EMB], g_xl[3][MTOT * EMB];   // split inputs Q,K,V
__device__ bf16 g_wh[4][EMB * EMB],  g_wl[4][EMB * EMB];    // split weights
__device__ bf16 g_ph[3][MTOT * EMB], g_pl[3][MTOT * EMB];   // split projections q,k,v
__device__ bf16 g_ch[MTOT * EMB],    g_cl[MTOT * EMB];      // split attention ctx

__device__ __forceinline__ uint32_t pack2(float a, float b) {
    __nv_bfloat162 t = __floats2bfloat162_rn(a, b);
    return *reinterpret_cast<uint32_t*>(&t);
}
__device__ __forceinline__ void ldm_x4(uint32_t& r0, uint32_t& r1,
                                       uint32_t& r2, uint32_t& r3, uint32_t addr) {
    asm volatile("ldmatrix.sync.aligned.m8n8.x4.shared.b16 {%0,%1,%2,%3}, [%4];"
                 : "=r"(r0), "=r"(r1), "=r"(r2), "=r"(r3) : "r"(addr));
}
__device__ __forceinline__ void ldm_x4_t(uint32_t& r0, uint32_t& r1,
                                         uint32_t& r2, uint32_t& r3, uint32_t addr) {
    asm volatile("ldmatrix.sync.aligned.m8n8.x4.trans.shared.b16 {%0,%1,%2,%3}, [%4];"
                 : "=r"(r0), "=r"(r1), "=r"(r2), "=r"(r3) : "r"(addr));
}
__device__ __forceinline__ void mma16816(float& c0, float& c1, float& c2, float& c3,
                                         uint32_t a0, uint32_t a1, uint32_t a2, uint32_t a3,
                                         uint32_t b0, uint32_t b1) {
    asm volatile("mma.sync.aligned.m16n8k16.row.col.f32.bf16.bf16.f32 "
                 "{%0,%1,%2,%3},{%4,%5,%6,%7},{%8,%9},{%0,%1,%2,%3};"
                 : "+f"(c0), "+f"(c1), "+f"(c2), "+f"(c3)
                 : "r"(a0), "r"(a1), "r"(a2), "r"(a3), "r"(b0), "r"(b1));
}
__device__ __forceinline__ void cp16(uint32_t saddr, const void* gaddr) {
    asm volatile("cp.async.cg.shared.global [%0], [%1], 16;" :: "r"(saddr), "l"(gaddr));
}
__device__ __forceinline__ void cp_commit() { asm volatile("cp.async.commit_group;"); }
template <int N>
__device__ __forceinline__ void cp_wait() { asm volatile("cp.async.wait_group %0;" :: "n"(N)); }

// ---------------------------------------------------------------------------
// split: fp32 -> (hi, lo) bf16 planes
// ---------------------------------------------------------------------------
__global__ __launch_bounds__(256) void split_f32(const float* __restrict__ X,
                                                 bf16* __restrict__ Xh,
                                                 bf16* __restrict__ Xl, int n4)
{
    int i = blockIdx.x * blockDim.x + threadIdx.x;
    if (i >= n4) return;
    float4 f = ((const float4*)X)[i];
    float h0 = __bfloat162float(__float2bfloat16_rn(f.x));
    float h1 = __bfloat162float(__float2bfloat16_rn(f.y));
    float h2 = __bfloat162float(__float2bfloat16_rn(f.z));
    float h3 = __bfloat162float(__float2bfloat16_rn(f.w));
    ((uint2*)Xh)[i] = make_uint2(pack2(f.x, f.y), pack2(f.z, f.w));
    ((uint2*)Xl)[i] = make_uint2(pack2(f.x - h0, f.y - h1), pack2(f.z - h2, f.w - h3));
}

// ---------------------------------------------------------------------------
// Split-bf16 GEMM (R4, validated):  C = A*B^T on pre-split planes.
// ---------------------------------------------------------------------------
#define SSTR 40
#define GSTG 40960u
#define GPL  10240u

template <int MODE>
__global__ __launch_bounds__(256) void gemm_nt_split(
    const bf16* __restrict__ Ah, const bf16* __restrict__ Al,
    const bf16* __restrict__ Bh, const bf16* __restrict__ Bl,
    float* __restrict__ C, bf16* __restrict__ Ch, bf16* __restrict__ Cl)
{
    const int K = EMB, N = EMB;
    extern __shared__ bf16 smem[];
    uint32_t sbase = (uint32_t)__cvta_generic_to_shared(smem);

    const int tid  = threadIdx.x;
    const int lane = tid & 31;
    const int wid  = tid >> 5;
    const int wm = (wid & 1) * 64;
    const int wn = (wid >> 1) * 32;
    const int bm = blockIdx.y * 128;
    const int bn = blockIdx.x * 128;

    const bf16* Aph = Ah + (size_t)bm * K;
    const bf16* Apl = Al + (size_t)bm * K;
    const bf16* Bph = Bh + (size_t)bn * K;
    const bf16* Bpl = Bl + (size_t)bn * K;

    const int cr = tid >> 2;
    const int cc = (tid & 3) * 8;
    const int lrow = lane & 15;
    const int lcol = (lane >> 4) << 3;

    float acc[4][4][4];
#pragma unroll
    for (int i = 0; i < 4; i++)
#pragma unroll
        for (int j = 0; j < 4; j++)
#pragma unroll
            for (int c = 0; c < 4; c++) acc[i][j][c] = 0.f;

#define GISSUE(k0, stg) {                                                      \
        uint32_t sb = sbase + (uint32_t)(stg) * GSTG;                          \
        size_t go1 = (size_t)cr * K + (size_t)(k0) + cc;                       \
        size_t go2 = (size_t)(cr + 64) * K + (size_t)(k0) + cc;                \
        uint32_t so1 = (uint32_t)(cr * SSTR + cc) * 2u;                        \
        uint32_t so2 = (uint32_t)((cr + 64) * SSTR + cc) * 2u;                 \
        cp16(sb + so1,            Aph + go1);                                  \
        cp16(sb + so2,            Aph + go2);                                  \
        cp16(sb + GPL + so1,      Apl + go1);                                  \
        cp16(sb + GPL + so2,      Apl + go2);                                  \
        cp16(sb + 2 * GPL + so1,  Bph + go1);                                  \
        cp16(sb + 2 * GPL + so2,  Bph + go2);                                  \
        cp16(sb + 3 * GPL + so1,  Bpl + go1);                                  \
        cp16(sb + 3 * GPL + so2,  Bpl + go2);                                  \
    }

    GISSUE(0, 0); cp_commit();

    const int NIT = K / 32;
    for (int it = 0; it < NIT; it++) {
        const int s = it & 1;
        if (it + 1 < NIT) { GISSUE((it + 1) * 32, s ^ 1); cp_commit(); cp_wait<1>(); }
        else              { cp_wait<0>(); }
        __syncthreads();

        uint32_t bAh = sbase + (uint32_t)s * GSTG;
        uint32_t bAl = bAh + GPL;
        uint32_t bBh = bAh + 2 * GPL;
        uint32_t bBl = bAh + 3 * GPL;

#pragma unroll
        for (int ks = 0; ks < 32; ks += 16) {
            uint32_t bh[2][4], bl[2][4];
#pragma unroll
            for (int p = 0; p < 2; p++) {
                uint32_t off = (uint32_t)((wn + p * 16 + lrow) * SSTR + ks + lcol) * 2;
                ldm_x4(bh[p][0], bh[p][1], bh[p][2], bh[p][3], bBh + off);
                ldm_x4(bl[p][0], bl[p][1], bl[p][2], bl[p][3], bBl + off);
            }
#pragma unroll
            for (int mt = 0; mt < 4; mt++) {
                uint32_t off = (uint32_t)((wm + mt * 16 + lrow) * SSTR + ks + lcol) * 2;
                uint32_t ah0, ah1, ah2, ah3, al0, al1, al2, al3;
                ldm_x4(ah0, ah1, ah2, ah3, bAh + off);
                ldm_x4(al0, al1, al2, al3, bAl + off);
#pragma unroll
                for (int p = 0; p < 2; p++) {
                    float* c0 = acc[mt][p * 2];
                    mma16816(c0[0], c0[1], c0[2], c0[3],
                             ah0, ah1, ah2, ah3, bh[p][0], bh[p][2]);
                    mma16816(c0[0], c0[1], c0[2], c0[3],
                             al0, al1, al2, al3, bh[p][0], bh[p][2]);
                    mma16816(c0[0], c0[1], c0[2], c0[3],
                             ah0, ah1, ah2, ah3, bl[p][0], bl[p][2]);
                    float* c1 = acc[mt][p * 2 + 1];
                    mma16816(c1[0], c1[1], c1[2], c1[3],
                             ah0, ah1, ah2, ah3, bh[p][1], bh[p][3]);
                    mma16816(c1[0], c1[1], c1[2], c1[3],
                             al0, al1, al2, al3, bh[p][1], bh[p][3]);
                    mma16816(c1[0], c1[1], c1[2], c1[3],
                             ah0, ah1, ah2, ah3, bl[p][1], bl[p][3]);
                }
            }
        }
        __syncthreads();
    }

#pragma unroll
    for (int mt = 0; mt < 4; mt++) {
#pragma unroll
        for (int nt = 0; nt < 4; nt++) {
            int gr = bm + wm + mt * 16 + (lane >> 2);
            int gc = bn + wn + nt * 8 + (lane & 3) * 2;
            float* c = acc[mt][nt];
            if (MODE == 0) {
                *(float2*)(C + (size_t)gr * N + gc)       = make_float2(c[0], c[1]);
                *(float2*)(C + (size_t)(gr + 8) * N + gc) = make_float2(c[2], c[3]);
            } else {
                float h0 = __bfloat162float(__float2bfloat16_rn(c[0]));
                float h1 = __bfloat162float(__float2bfloat16_rn(c[1]));
                float h2 = __bfloat162float(__float2bfloat16_rn(c[2]));
                float h3 = __bfloat162float(__float2bfloat16_rn(c[3]));
                *(uint32_t*)(Ch + (size_t)gr * N + gc)       = pack2(c[0], c[1]);
                *(uint32_t*)(Cl + (size_t)gr * N + gc)       = pack2(c[0] - h0, c[1] - h1);
                *(uint32_t*)(Ch + (size_t)(gr + 8) * N + gc) = pack2(c[2], c[3]);
                *(uint32_t*)(Cl + (size_t)(gr + 8) * N + gc) = pack2(c[2] - h2, c[3] - h3);
            }
        }
    }
#undef GISSUE
}

// ---------------------------------------------------------------------------
// Pipelined tensor-core flash attention: 3-stage cp.async ring; QK computed
// one tile AHEAD so softmax(t) overlaps QK(t+1) HMMAs on the tensor pipe.
// grid = (S/128, B*H), block = 256. BC = 64. Dynamic smem 108 KB.
// ---------------------------------------------------------------------------
#define FSTR 72
#define FSTG 36864u
#define FPL  9216u

__global__ __launch_bounds__(256) void flash_attn_tc3(
    const bf16* __restrict__ qh, const bf16* __restrict__ ql,
    const bf16* __restrict__ kh, const bf16* __restrict__ kl,
    const bf16* __restrict__ vh, const bf16* __restrict__ vl,
    bf16* __restrict__ ch, bf16* __restrict__ cl)
{
    extern __shared__ bf16 fsmem[];
    uint32_t fsbase = (uint32_t)__cvta_generic_to_shared(fsmem);

    const int tid  = threadIdx.x;
    const int lane = tid & 31;
    const int wid  = tid >> 5;
    const int g    = lane >> 2;
    const int q2   = (lane & 3) * 2;

    const int bh_ = blockIdx.y;
    const int b = bh_ >> 4;
    const int h = bh_ & 15;

    const int lrow = lane & 15;
    const int lcol = (lane >> 4) << 3;

    const bf16* Khp = kh + (size_t)(b * S_LEN) * EMB + h * DK;
    const bf16* Klp = kl + (size_t)(b * S_LEN) * EMB + h * DK;
    const bf16* Vhp = vh + (size_t)(b * S_LEN) * EMB + h * DK;
    const bf16* Vlp = vl + (size_t)(b * S_LEN) * EMB + h * DK;

    const int fr = tid >> 3;
    const int fc = (tid & 7) * 8;

    // ---- Q fragments (hi/lo, pre-scaled by 1/8)
    uint32_t Qh[4][4], Ql[4][4];
    {
        const int r0 = b * S_LEN + blockIdx.x * 128 + wid * 16 + g;
        const bf16* q0h = qh + (size_t)r0 * EMB + h * DK;
        const bf16* q0l = ql + (size_t)r0 * EMB + h * DK;
        const __nv_bfloat162 sc = __floats2bfloat162_rn(0.125f, 0.125f);
#pragma unroll
        for (int s = 0; s < 4; s++) {
#pragma unroll
            for (int half = 0; half < 2; half++) {
                int c = s * 16 + half * 8 + q2;
                __nv_bfloat162 t;
                t = __hmul2(*(const __nv_bfloat162*)(q0h + c), sc);
                Qh[s][half * 2 + 0] = *(uint32_t*)&t;
                t = __hmul2(*(const __nv_bfloat162*)(q0h + 8 * EMB + c), sc);
                Qh[s][half * 2 + 1] = *(uint32_t*)&t;
                t = __hmul2(*(const __nv_bfloat162*)(q0l + c), sc);
                Ql[s][half * 2 + 0] = *(uint32_t*)&t;
                t = __hmul2(*(const __nv_bfloat162*)(q0l + 8 * EMB + c), sc);
                Ql[s][half * 2 + 1] = *(uint32_t*)&t;
            }
        }
    }

    float oacc[8][4];
#pragma unroll
    for (int i = 0; i < 8; i++)
#pragma unroll
        for (int c = 0; c < 4; c++) oacc[i][c] = 0.f;
    float m0 = -1e30f, m1 = -1e30f, l0 = 0.f, l1 = 0.f;

    float sA[8][4], sB[8][4];   // double-buffered score fragments

#define FISSUE(t0, stg) {                                                      \
        uint32_t sb = fsbase + (uint32_t)(stg) * FSTG;                         \
        size_t go1 = (size_t)((t0) + fr) * EMB + fc;                           \
        size_t go2 = (size_t)((t0) + fr + 32) * EMB + fc;                      \
        uint32_t so1 = (uint32_t)(fr * FSTR + fc) * 2u;                        \
        uint32_t so2 = (uint32_t)((fr + 32) * FSTR + fc) * 2u;                 \
        cp16(sb + so1,           Khp + go1);                                   \
        cp16(sb + so2,           Khp + go2);                                   \
        cp16(sb + FPL + so1,     Klp + go1);                                   \
        cp16(sb + FPL + so2,     Klp + go2);                                   \
        cp16(sb + 2 * FPL + so1, Vhp + go1);                                   \
        cp16(sb + 2 * FPL + so2, Vhp + go2);                                   \
        cp16(sb + 3 * FPL + so1, Vlp + go1);                                   \
        cp16(sb + 3 * FPL + so2, Vlp + go2);                                   \
    }

// QK of one 64-key tile into score fragments `dst` from smem stage `stg`.
#define QKCOMP(dst, stg) {                                                     \
        uint32_t bKh = fsbase + (uint32_t)(stg) * FSTG;                        \
        uint32_t bKl = bKh + FPL;                                              \
        _Pragma("unroll")                                                      \
        for (int i = 0; i < 8; i++)                                            \
            { dst[i][0] = 0.f; dst[i][1] = 0.f; dst[i][2] = 0.f; dst[i][3] = 0.f; } \
        _Pragma("unroll")                                                      \
        for (int np = 0; np < 4; np++) {                                       \
            _Pragma("unroll")                                                  \
            for (int sk = 0; sk < 4; sk++) {                                   \
                uint32_t off = (uint32_t)((np * 16 + lrow) * FSTR + sk * 16 + lcol) * 2; \
                uint32_t kh0, kh1, kh2, kh3, kl0, kl1, kl2, kl3;               \
                ldm_x4(kh0, kh1, kh2, kh3, bKh + off);                         \
                ldm_x4(kl0, kl1, kl2, kl3, bKl + off);                         \
                float* c0 = dst[np * 2];                                       \
                mma16816(c0[0], c0[1], c0[2], c0[3],                           \
                         Qh[sk][0], Qh[sk][1], Qh[sk][2], Qh[sk][3], kh0, kh2);\
                mma16816(c0[0], c0[1], c0[2], c0[3],                           \
                         Ql[sk][0], Ql[sk][1], Ql[sk][2], Ql[sk][3], kh0, kh2);\
                mma16816(c0[0], c0[1], c0[2], c0[3],                           \
                         Qh[sk][0], Qh[sk][1], Qh[sk][2], Qh[sk][3], kl0, kl2);\
                float* c1 = dst[np * 2 + 1];                                   \
                mma16816(c1[0], c1[1], c1[2], c1[3],                           \
                         Qh[sk][0], Qh[sk][1], Qh[sk][2], Qh[sk][3], kh1, kh3);\
                mma16816(c1[0], c1[1], c1[2], c1[3],                           \
                         Ql[sk][0], Ql[sk][1], Ql[sk][2], Ql[sk][3], kh1, kh3);\
                mma16816(c1[0], c1[1], c1[2], c1[3],                           \
                         Qh[sk][0], Qh[sk][1], Qh[sk][2], Qh[sk][3], kl1, kl3);\
            }                                                                  \
        }                                                                      \
    }

// One pipeline iteration: consumes scores `cur` (tile t), precomputes `nxt`
// (tile t+1), accumulates PV for tile t.
#define FBODY(cur, nxt, t) {                                                   \
        if ((t) + 2 < NIT) { FISSUE(((t) + 2) * 64, ((t) + 2) % 3); cp_commit(); } \
        if ((t) + 2 < NIT) { cp_wait<1>(); } else { cp_wait<0>(); }            \
        __syncthreads();                                                       \
        if ((t) + 1 < NIT) QKCOMP(nxt, ((t) + 1) % 3);                         \
        float tm0 = -1e30f, tm1 = -1e30f;                                      \
        _Pragma("unroll")                                                      \
        for (int i = 0; i < 8; i++) {                                          \
            tm0 = fmaxf(tm0, fmaxf(cur[i][0], cur[i][1]));                     \
            tm1 = fmaxf(tm1, fmaxf(cur[i][2], cur[i][3]));                     \
        }                                                                      \
        tm0 = fmaxf(tm0, __shfl_xor_sync(0xffffffffu, tm0, 1));                \
        tm0 = fmaxf(tm0, __shfl_xor_sync(0xffffffffu, tm0, 2));                \
        tm1 = fmaxf(tm1, __shfl_xor_sync(0xffffffffu, tm1, 1));                \
        tm1 = fmaxf(tm1, __shfl_xor_sync(0xffffffffu, tm1, 2));                \
        float mn0 = fmaxf(m0, tm0);                                            \
        float mn1 = fmaxf(m1, tm1);                                            \
        float cr0 = __expf(m0 - mn0);                                          \
        float cr1 = __expf(m1 - mn1);                                          \
        m0 = mn0; m1 = mn1;                                                    \
        l0 *= cr0; l1 *= cr1;                                                  \
        _Pragma("unroll")                                                      \
        for (int i = 0; i < 8; i++) {                                          \
            oacc[i][0] *= cr0; oacc[i][1] *= cr0;                              \
            oacc[i][2] *= cr1; oacc[i][3] *= cr1;                              \
        }                                                                      \
        _Pragma("unroll")                                                      \
        for (int i = 0; i < 8; i++) {                                          \
            float p0 = __expf(cur[i][0] - mn0);                                \
            float p1 = __expf(cur[i][1] - mn0);                                \
            float p2 = __expf(cur[i][2] - mn1);                                \
            float p3 = __expf(cur[i][3] - mn1);                                \
            cur[i][0] = p0; cur[i][1] = p1; cur[i][2] = p2; cur[i][3] = p3;    \
            l0 += p0 + p1; l1 += p2 + p3;                                      \
        }                                                                      \
        uint32_t bVh = fsbase + (uint32_t)((t) % 3) * FSTG + 2 * FPL;          \
        uint32_t bVl = bVh + FPL;                                              \
        _Pragma("unroll")                                                      \
        for (int ks = 0; ks < 4; ks++) {                                       \
            float* pA = cur[2 * ks];                                           \
            float* pB = cur[2 * ks + 1];                                       \
            float hA0 = __bfloat162float(__float2bfloat16_rn(pA[0]));          \
            float hA1 = __bfloat162float(__float2bfloat16_rn(pA[1]));          \
            float hA2 = __bfloat162float(__float2bfloat16_rn(pA[2]));          \
            float hA3 = __bfloat162float(__float2bfloat16_rn(pA[3]));          \
            float hB0 = __bfloat162float(__float2bfloat16_rn(pB[0]));          \
            float hB1 = __bfloat162float(__float2bfloat16_rn(pB[1]));          \
            float hB2 = __bfloat162float(__float2bfloat16_rn(pB[2]));          \
            float hB3 = __bfloat162float(__float2bfloat16_rn(pB[3]));          \
            uint32_t ah0 = pack2(pA[0], pA[1]);                                \
            uint32_t ah1 = pack2(pA[2], pA[3]);                                \
            uint32_t ah2 = pack2(pB[0], pB[1]);                                \
            uint32_t ah3 = pack2(pB[2], pB[3]);                                \
            uint32_t al0 = pack2(pA[0] - hA0, pA[1] - hA1);                    \
            uint32_t al1 = pack2(pA[2] - hA2, pA[3] - hA3);                    \
            uint32_t al2 = pack2(pB[0] - hB0, pB[1] - hB1);                    \
            uint32_t al3 = pack2(pB[2] - hB2, pB[3] - hB3);                    \
            _Pragma("unroll")                                                  \
            for (int np = 0; np < 4; np++) {                                   \
                uint32_t off = (uint32_t)((ks * 16 + lrow) * FSTR + np * 16 + lcol) * 2; \
                uint32_t vh0, vh1, vh2, vh3, vl0, vl1, vl2, vl3;               \
                ldm_x4_t(vh0, vh1, vh2, vh3, bVh + off);                       \
                ldm_x4_t(vl0, vl1, vl2, vl3, bVl + off);                       \
                float* c0 = oacc[np * 2];                                      \
                mma16816(c0[0], c0[1], c0[2], c0[3], ah0, ah1, ah2, ah3, vh0, vh1); \
                mma16816(c0[0], c0[1], c0[2], c0[3], al0, al1, al2, al3, vh0, vh1); \
                mma16816(c0[0], c0[1], c0[2], c0[3], ah0, ah1, ah2, ah3, vl0, vl1); \
                float* c1 = oacc[np * 2 + 1];                                  \
                mma16816(c1[0], c1[1], c1[2], c1[3], ah0, ah1, ah2, ah3, vh2, vh3); \
                mma16816(c1[0], c1[1], c1[2], c1[3], al0, al1, al2, al3, vh2, vh3); \
                mma16816(c1[0], c1[1], c1[2], c1[3], ah0, ah1, ah2, ah3, vl2, vl3); \
            }                                                                  \
        }                                                                      \
        __syncthreads();                                                       \
    }

    const int NIT = S_LEN / 64;  // 32 (even)

    // prologue: stages 0,1 in flight; QK(0) once stage 0 lands
    FISSUE(0, 0); cp_commit();
    FISSUE(64, 1); cp_commit();
    cp_wait<1>();
    __syncthreads();
    QKCOMP(sA, 0);

    for (int t = 0; t < NIT; t += 2) {
        FBODY(sA, sB, t);
        FBODY(sB, sA, t + 1);
    }

    // ---- finalize -> ctx hi/lo planes
    l0 += __shfl_xor_sync(0xffffffffu, l0, 1);
    l0 += __shfl_xor_sync(0xffffffffu, l0, 2);
    l1 += __shfl_xor_sync(0xffffffffu, l1, 1);
    l1 += __shfl_xor_sync(0xffffffffu, l1, 2);
    float inv0 = 1.0f / l0;
    float inv1 = 1.0f / l1;

    const int r0 = b * S_LEN + blockIdx.x * 128 + wid * 16 + g;
    bf16* o0h = ch + (size_t)r0 * EMB + h * DK;
    bf16* o0l = cl + (size_t)r0 * EMB + h * DK;
#pragma unroll
    for (int nt = 0; nt < 8; nt++) {
        int n = nt * 8 + q2;
        float f0 = oacc[nt][0] * inv0, f1 = oacc[nt][1] * inv0;
        float f2 = oacc[nt][2] * inv1, f3 = oacc[nt][3] * inv1;
        float h0 = __bfloat162float(__float2bfloat16_rn(f0));
        float h1 = __bfloat162float(__float2bfloat16_rn(f1));
        float h2 = __bfloat162float(__float2bfloat16_rn(f2));
        float h3 = __bfloat162float(__float2bfloat16_rn(f3));
        *(uint32_t*)(o0h + n)           = pack2(f0, f1);
        *(uint32_t*)(o0l + n)           = pack2(f0 - h0, f1 - h1);
        *(uint32_t*)(o0h + 8 * EMB + n) = pack2(f2, f3);
        *(uint32_t*)(o0l + 8 * EMB + n) = pack2(f2 - h2, f3 - h3);
    }
#undef FISSUE
#undef QKCOMP
#undef FBODY
}

// ---------------------------------------------------------------------------
extern "C" void kernel_launch(void* const* d_in, const int* in_sizes, int n_in,
                              void* d_out, int out_size)
{
    (void)in_sizes; (void)n_in; (void)out_size;
    const float* IN[3] = {(const float*)d_in[0], (const float*)d_in[1], (const float*)d_in[2]};
    const float* W[4]  = {(const float*)d_in[4], (const float*)d_in[5],
                          (const float*)d_in[6], (const float*)d_in[7]};
    float* out = (float*)d_out;

    bf16 *xh, *xl, *wh, *wl, *ph, *pl, *chp, *clp;
    cudaGetSymbolAddress((void**)&xh, g_xh);
    cudaGetSymbolAddress((void**)&xl, g_xl);
    cudaGetSymbolAddress((void**)&wh, g_wh);
    cudaGetSymbolAddress((void**)&wl, g_wl);
    cudaGetSymbolAddress((void**)&ph, g_ph);
    cudaGetSymbolAddress((void**)&pl, g_pl);
    cudaGetSymbolAddress((void**)&chp, g_ch);
    cudaGetSymbolAddress((void**)&clp, g_cl);

    const int GSM = 2 * (int)GSTG;   // 81920
    const int FSM = 3 * (int)FSTG;   // 110592
    cudaFuncSetAttribute(gemm_nt_split<0>, cudaFuncAttributeMaxDynamicSharedMemorySize, GSM);
    cudaFuncSetAttribute(gemm_nt_split<1>, cudaFuncAttributeMaxDynamicSharedMemorySize, GSM);
    cudaFuncSetAttribute(flash_attn_tc3,  cudaFuncAttributeMaxDynamicSharedMemorySize, FSM);

    const int n4i = MTOT * EMB / 4;
    const int n4w = EMB * EMB / 4;
    for (int i = 0; i < 3; i++)
        split_f32<<<(n4i + 255) / 256, 256>>>(IN[i], xh + (size_t)i * MTOT * EMB,
                                              xl + (size_t)i * MTOT * EMB, n4i);
    for (int i = 0; i < 4; i++)
        split_f32<<<(n4w + 255) / 256, 256>>>(W[i], wh + (size_t)i * EMB * EMB,
                                              wl + (size_t)i * EMB * EMB, n4w);

    dim3 gg(EMB / 128, MTOT / 128);   // (8, 64)
    for (int i = 0; i < 3; i++)
        gemm_nt_split<1><<<gg, 256, GSM>>>(xh + (size_t)i * MTOT * EMB,
                                           xl + (size_t)i * MTOT * EMB,
                                           wh + (size_t)i * EMB * EMB,
                                           wl + (size_t)i * EMB * EMB,
                                           nullptr,
                                           ph + (size_t)i * MTOT * EMB,
                                           pl + (size_t)i * MTOT * EMB);

    dim3 ga(S_LEN / 128, BATCH * NH); // (16, 64)
    flash_attn_tc3<<<ga, 256, FSM>>>(ph, pl,
                                     ph + (size_t)MTOT * EMB, pl + (size_t)MTOT * EMB,
                                     ph + (size_t)2 * MTOT * EMB, pl + (size_t)2 * MTOT * EMB,
                                     chp, clp);

    gemm_nt_split<0><<<gg, 256, GSM>>>(chp, clp,
                                       wh + (size_t)3 * EMB * EMB,
                                       wl + (size_t)3 * EMB * EMB,
                                       out, nullptr, nullptr);
}